// round 2
// baseline (speedup 1.0000x reference)
#include <cuda_runtime.h>
#include <cstddef>
#include <cstdint>

// Problem constants
#define B_ 8
#define N_ 784
#define C_ 768
#define H_ 16
#define D_ 48
#define S_ 28
#define M_ (B_ * N_)          // 6272 rows
#define SCALE_ 0.14433756729740643f  // 48^-0.5

// ---------------- scratch (device globals; no allocation allowed) ----------
__device__ float g_qkv[(size_t)M_ * 3 * C_];   // [M, 3C] : q | k | v
__device__ float g_pos[(size_t)H_ * N_ * N_];  // softmaxed positional scores
__device__ float g_o[(size_t)M_ * C_];         // attention output pre-projection

// ---------------- QKV GEMM: g_qkv[i, z*C + j] = sum_k x[i,k] * W_z[j,k] ----
#define BM 64
#define BN 64
#define BK 16

__global__ void __launch_bounds__(256) qkv_gemm(const float* __restrict__ x,
                                                const float* __restrict__ Wq,
                                                const float* __restrict__ Wk,
                                                const float* __restrict__ Wv) {
    __shared__ float As[BK][BM + 4];
    __shared__ float Bs[BK][BN + 4];
    const int tid = threadIdx.x;
    const int tx = tid & 15;
    const int ty = tid >> 4;
    const int i0 = blockIdx.y * BM;
    const int j0 = blockIdx.x * BN;
    const int z = blockIdx.z;               // 0=q 1=k 2=v
    const float* Bw = (z == 0) ? Wq : (z == 1) ? Wk : Wv;
    const float* Ab = x + (size_t)i0 * C_;
    const float* Bb = Bw + (size_t)j0 * C_;
    const int lr = tid >> 2;          // 0..63
    const int lc = (tid & 3) << 2;    // 0,4,8,12

    float acc[4][4] = {};

    for (int k0 = 0; k0 < C_; k0 += BK) {
        float4 a4 = *(const float4*)(Ab + (size_t)lr * C_ + k0 + lc);
        float4 b4 = *(const float4*)(Bb + (size_t)lr * C_ + k0 + lc);
        As[lc + 0][lr] = a4.x; As[lc + 1][lr] = a4.y;
        As[lc + 2][lr] = a4.z; As[lc + 3][lr] = a4.w;
        Bs[lc + 0][lr] = b4.x; Bs[lc + 1][lr] = b4.y;
        Bs[lc + 2][lr] = b4.z; Bs[lc + 3][lr] = b4.w;
        __syncthreads();
#pragma unroll
        for (int kk = 0; kk < BK; kk++) {
            float4 av = *(const float4*)&As[kk][ty * 4];
            float4 bv = *(const float4*)&Bs[kk][tx * 4];
            float a[4] = {av.x, av.y, av.z, av.w};
            float b[4] = {bv.x, bv.y, bv.z, bv.w};
#pragma unroll
            for (int r = 0; r < 4; r++) {
#pragma unroll
                for (int c = 0; c < 4; c++) acc[r][c] += a[r] * b[c];
            }
        }
        __syncthreads();
    }

#pragma unroll
    for (int r = 0; r < 4; r++) {
        float* crow = g_qkv + (size_t)(i0 + ty * 4 + r) * (3 * C_) + z * C_ + j0 + tx * 4;
#pragma unroll
        for (int c = 0; c < 4; c++) crow[c] = acc[r][c];
    }
}

// ---------------- projection GEMM: out = g_o @ Wproj^T + b ------------------
__global__ void __launch_bounds__(256) proj_gemm(const float* __restrict__ Wp,
                                                 const float* __restrict__ bias,
                                                 float* __restrict__ Cmat) {
    __shared__ float As[BK][BM + 4];
    __shared__ float Bs[BK][BN + 4];
    const int tid = threadIdx.x;
    const int tx = tid & 15;
    const int ty = tid >> 4;
    const int i0 = blockIdx.y * BM;
    const int j0 = blockIdx.x * BN;
    const float* Ab = g_o + (size_t)i0 * C_;
    const float* Bb = Wp + (size_t)j0 * C_;
    const int lr = tid >> 2;
    const int lc = (tid & 3) << 2;

    float acc[4][4] = {};

    for (int k0 = 0; k0 < C_; k0 += BK) {
        float4 a4 = *(const float4*)(Ab + (size_t)lr * C_ + k0 + lc);
        float4 b4 = *(const float4*)(Bb + (size_t)lr * C_ + k0 + lc);
        As[lc + 0][lr] = a4.x; As[lc + 1][lr] = a4.y;
        As[lc + 2][lr] = a4.z; As[lc + 3][lr] = a4.w;
        Bs[lc + 0][lr] = b4.x; Bs[lc + 1][lr] = b4.y;
        Bs[lc + 2][lr] = b4.z; Bs[lc + 3][lr] = b4.w;
        __syncthreads();
#pragma unroll
        for (int kk = 0; kk < BK; kk++) {
            float4 av = *(const float4*)&As[kk][ty * 4];
            float4 bv = *(const float4*)&Bs[kk][tx * 4];
            float a[4] = {av.x, av.y, av.z, av.w};
            float b[4] = {bv.x, bv.y, bv.z, bv.w};
#pragma unroll
            for (int r = 0; r < 4; r++) {
#pragma unroll
                for (int c = 0; c < 4; c++) acc[r][c] += a[r] * b[c];
            }
        }
        __syncthreads();
    }

#pragma unroll
    for (int r = 0; r < 4; r++) {
        float* crow = Cmat + (size_t)(i0 + ty * 4 + r) * C_ + j0 + tx * 4;
#pragma unroll
        for (int c = 0; c < 4; c++) crow[c] = acc[r][c] + bias[j0 + tx * 4 + c];
    }
}

// ---------------- positional scores: softmax over m of (rel . W_pos + b) ---
__global__ void __launch_bounds__(256) pos_kernel(const float* __restrict__ W_pos,
                                                  const float* __restrict__ b_pos) {
    const int n = blockIdx.x;
    const int h = blockIdx.y;
    const int i1 = n / S_;
    const int j1 = n % S_;
    const float w0 = W_pos[h * 3 + 0];
    const float w1 = W_pos[h * 3 + 1];
    const float w2 = W_pos[h * 3 + 2];
    const float bp = b_pos[h];

    __shared__ float buf[N_];
    __shared__ float red[256];
    const int tid = threadIdx.x;

    float lmax = -1e30f;
    for (int m = tid; m < N_; m += 256) {
        float dx = (float)(m % S_ - j1);
        float dy = (float)(m / S_ - i1);
        float l = w0 * dx + w1 * dy + w2 * (dx * dx + dy * dy) + bp;
        buf[m] = l;
        lmax = fmaxf(lmax, l);
    }
    red[tid] = lmax;
    __syncthreads();
    for (int s = 128; s > 0; s >>= 1) {
        if (tid < s) red[tid] = fmaxf(red[tid], red[tid + s]);
        __syncthreads();
    }
    const float mx = red[0];
    __syncthreads();

    float lsum = 0.f;
    for (int m = tid; m < N_; m += 256) {
        float e = __expf(buf[m] - mx);
        buf[m] = e;
        lsum += e;
    }
    red[tid] = lsum;
    __syncthreads();
    for (int s = 128; s > 0; s >>= 1) {
        if (tid < s) red[tid] += red[tid + s];
        __syncthreads();
    }
    const float inv = 1.f / red[0];
    __syncthreads();

    float* row = g_pos + ((size_t)h * N_ + n) * N_;
    for (int m = tid; m < N_; m += 256) row[m] = buf[m] * inv;
}

// ---------------- repack V into output region [b,h,n,d] --------------------
__global__ void __launch_bounds__(256) repack_v(float* __restrict__ vout) {
    int idx = blockIdx.x * 256 + threadIdx.x;
    if (idx >= M_ * C_) return;
    int i = idx / C_;
    int j = idx % C_;
    int b = i / N_;
    int n = i % N_;
    int h = j / D_;
    int dd = j % D_;
    vout[((size_t)(b * H_ + h) * N_ + n) * D_ + dd] =
        g_qkv[(size_t)i * (3 * C_) + 2 * C_ + j];
}

// ---------------- fused attention -----------------------------------------
// block = (ntile, h, b); 16 rows per block; 256 threads as (tx=16, ty=16).
// Thread (ty,tx) owns row n0+ty and columns m = c*112 + u*16 + tx (c<7,u<7).
#define CHUNK 112
#define KPAD 52

__global__ void __launch_bounds__(256, 1) attn_kernel(const float* __restrict__ gating,
                                                      float* __restrict__ attn_out) {
    const int ntile = blockIdx.x;   // 0..48
    const int h = blockIdx.y;
    const int b = blockIdx.z;
    const int tx = threadIdx.x;
    const int ty = threadIdx.y;
    const int tid = ty * 16 + tx;
    const int n = ntile * 16 + ty;

    __shared__ float Ks[CHUNK][KPAD];

    // ---- Q row into registers, pre-scaled
    float q[D_];
    {
        const float* qrow = g_qkv + (size_t)(b * N_ + n) * (3 * C_) + h * D_;
#pragma unroll
        for (int t = 0; t < 12; t++) {
            float4 v4 = *(const float4*)(qrow + 4 * t);
            q[4 * t + 0] = v4.x * SCALE_;
            q[4 * t + 1] = v4.y * SCALE_;
            q[4 * t + 2] = v4.z * SCALE_;
            q[4 * t + 3] = v4.w * SCALE_;
        }
    }

    float s[49];

    // ---- scores: S[n, m] = q . k_m
    for (int c = 0; c < 7; c++) {
        const int m0 = c * CHUNK;
        __syncthreads();
        for (int idx = tid; idx < CHUNK * 12; idx += 256) {
            int row = idx / 12;
            int c4 = idx % 12;
            float4 v4 = *(const float4*)(g_qkv + (size_t)(b * N_ + m0 + row) * (3 * C_) +
                                         C_ + h * D_ + c4 * 4);
            *(float4*)&Ks[row][c4 * 4] = v4;
        }
        __syncthreads();
#pragma unroll
        for (int u = 0; u < 7; u++) {
            const int krow = u * 16 + tx;
            float acc = 0.f;
#pragma unroll
            for (int t = 0; t < 12; t++) {
                float4 kv = *(const float4*)&Ks[krow][4 * t];
                acc += q[4 * t + 0] * kv.x;
                acc += q[4 * t + 1] * kv.y;
                acc += q[4 * t + 2] * kv.z;
                acc += q[4 * t + 3] * kv.w;
            }
            s[c * 7 + u] = acc;
        }
    }

    // ---- patch softmax over the row (reduce across the 16 tx lanes)
    float mx = -1e30f;
#pragma unroll
    for (int j = 0; j < 49; j++) mx = fmaxf(mx, s[j]);
#pragma unroll
    for (int off = 8; off > 0; off >>= 1)
        mx = fmaxf(mx, __shfl_xor_sync(0xffffffffu, mx, off));

    float esum = 0.f;
#pragma unroll
    for (int j = 0; j < 49; j++) {
        s[j] = __expf(s[j] - mx);
        esum += s[j];
    }
#pragma unroll
    for (int off = 8; off > 0; off >>= 1)
        esum += __shfl_xor_sync(0xffffffffu, esum, off);
    const float pinv = 1.f / esum;

    // ---- gate-combine with positional scores, renormalize
    const float gt = gating[h];
    const float g = 1.f / (1.f + __expf(-gt));
    const float* prow = g_pos + ((size_t)h * N_ + n) * N_;
    float asum = 0.f;
#pragma unroll
    for (int j = 0; j < 49; j++) {
        const int m = (j / 7) * CHUNK + (j % 7) * 16 + tx;
        float a = (1.f - g) * (s[j] * pinv) + g * prow[m];
        s[j] = a;
        asum += a;
    }
#pragma unroll
    for (int off = 8; off > 0; off >>= 1)
        asum += __shfl_xor_sync(0xffffffffu, asum, off);
    const float ainv = 1.f / asum;

    float* arow = attn_out + ((size_t)(b * H_ + h) * N_ + n) * N_;
#pragma unroll
    for (int j = 0; j < 49; j++) {
        const int m = (j / 7) * CHUNK + (j % 7) * 16 + tx;
        s[j] *= ainv;
        arow[m] = s[j];
    }

    // ---- AV: out[n, :] = sum_m attn[n,m] * v[m, :]
    float oacc[D_] = {};
    for (int c = 0; c < 7; c++) {
        const int m0 = c * CHUNK;
        __syncthreads();
        for (int idx = tid; idx < CHUNK * 12; idx += 256) {
            int row = idx / 12;
            int c4 = idx % 12;
            float4 v4 = *(const float4*)(g_qkv + (size_t)(b * N_ + m0 + row) * (3 * C_) +
                                         2 * C_ + h * D_ + c4 * 4);
            *(float4*)&Ks[row][c4 * 4] = v4;
        }
        __syncthreads();
#pragma unroll
        for (int u = 0; u < 7; u++) {
            const float a = s[c * 7 + u];
            const int vrow = u * 16 + tx;
#pragma unroll
            for (int t = 0; t < 12; t++) {
                float4 vv = *(const float4*)&Ks[vrow][4 * t];
                oacc[4 * t + 0] += a * vv.x;
                oacc[4 * t + 1] += a * vv.y;
                oacc[4 * t + 2] += a * vv.z;
                oacc[4 * t + 3] += a * vv.w;
            }
        }
    }

    // reduce across tx lanes (xor within 16-lane group), then lane tx==0 writes
#pragma unroll
    for (int d = 0; d < D_; d++) {
#pragma unroll
        for (int off = 8; off > 0; off >>= 1)
            oacc[d] += __shfl_xor_sync(0xffffffffu, oacc[d], off);
    }
    if (tx == 0) {
        float4* orow = (float4*)(g_o + (size_t)(b * N_ + n) * C_ + h * D_);
#pragma unroll
        for (int t = 0; t < 12; t++)
            orow[t] = make_float4(oacc[4 * t + 0], oacc[4 * t + 1],
                                  oacc[4 * t + 2], oacc[4 * t + 3]);
    }
}

// ---------------- launch ----------------------------------------------------
extern "C" void kernel_launch(void* const* d_in, const int* in_sizes, int n_in,
                              void* d_out, int out_size) {
    const float* x      = (const float*)d_in[0];
    const float* Wq     = (const float*)d_in[1];
    const float* Wk     = (const float*)d_in[2];
    const float* Wv     = (const float*)d_in[3];
    const float* Wproj  = (const float*)d_in[4];
    const float* b_proj = (const float*)d_in[5];
    const float* W_pos  = (const float*)d_in[6];
    const float* b_pos  = (const float*)d_in[7];
    const float* gating = (const float*)d_in[8];

    float* out_o    = (float*)d_out;                              // [B,N,C]
    float* out_attn = out_o + (size_t)B_ * N_ * C_;               // [B,H,N,N]
    float* out_v    = out_attn + (size_t)B_ * H_ * N_ * N_;       // [B,H,N,D]

    qkv_gemm<<<dim3(C_ / BN, M_ / BM, 3), 256>>>(x, Wq, Wk, Wv);

    pos_kernel<<<dim3(N_, H_), 256>>>(W_pos, b_pos);

    repack_v<<<(M_ * C_ + 255) / 256, 256>>>(out_v);

    attn_kernel<<<dim3(N_ / 16, H_, B_), dim3(16, 16)>>>(gating, out_attn);

    proj_gemm<<<dim3(C_ / BN, M_ / BM), 256>>>(Wproj, b_proj, out_o);
}

// round 3
// speedup vs baseline: 1.2651x; 1.2651x over previous
#include <cuda_runtime.h>
#include <cstddef>
#include <cstdint>

// Problem constants
#define B_ 8
#define N_ 784
#define C_ 768
#define H_ 16
#define D_ 48
#define S_ 28
#define M_ (B_ * N_)          // 6272 rows
#define SCALE_ 0.14433756729740643f  // 48^-0.5

// ---------------- scratch (device globals; no allocation allowed) ----------
__device__ float g_qkv[(size_t)M_ * 3 * C_];   // [M, 3C] : q | k | v
__device__ float g_pos[(size_t)H_ * N_ * N_];  // softmaxed positional scores
__device__ float g_o[(size_t)M_ * C_];         // attention output pre-projection

// ================= 128x128x16 SGEMM core (8x8 microtile) ====================
// As/Bs are [16][132] k-major transposed tiles.
__device__ __forceinline__ void sgemm_tile(const float* __restrict__ A,
                                           const float* __restrict__ Bw,
                                           int i0, int j0,
                                           float* As, float* Bs,
                                           float acc[8][8]) {
    const int tid = threadIdx.x;
    const int tx = tid & 15;
    const int ty = tid >> 4;
    const int r = tid >> 2;            // 0..63
    const int c4 = (tid & 3) << 2;     // 0,4,8,12

    for (int k0 = 0; k0 < C_; k0 += 16) {
#pragma unroll
        for (int l = 0; l < 2; l++) {
            const int rr = r + l * 64;
            float4 a4 = *(const float4*)(A + (size_t)(i0 + rr) * C_ + k0 + c4);
            float4 b4 = *(const float4*)(Bw + (size_t)(j0 + rr) * C_ + k0 + c4);
            As[(c4 + 0) * 132 + rr] = a4.x; As[(c4 + 1) * 132 + rr] = a4.y;
            As[(c4 + 2) * 132 + rr] = a4.z; As[(c4 + 3) * 132 + rr] = a4.w;
            Bs[(c4 + 0) * 132 + rr] = b4.x; Bs[(c4 + 1) * 132 + rr] = b4.y;
            Bs[(c4 + 2) * 132 + rr] = b4.z; Bs[(c4 + 3) * 132 + rr] = b4.w;
        }
        __syncthreads();
#pragma unroll
        for (int kk = 0; kk < 16; kk++) {
            float4 a0 = *(const float4*)&As[kk * 132 + ty * 8];
            float4 a1 = *(const float4*)&As[kk * 132 + ty * 8 + 4];
            float4 b0 = *(const float4*)&Bs[kk * 132 + tx * 8];
            float4 b1 = *(const float4*)&Bs[kk * 132 + tx * 8 + 4];
            float av[8] = {a0.x, a0.y, a0.z, a0.w, a1.x, a1.y, a1.z, a1.w};
            float bv[8] = {b0.x, b0.y, b0.z, b0.w, b1.x, b1.y, b1.z, b1.w};
#pragma unroll
            for (int rr = 0; rr < 8; rr++)
#pragma unroll
                for (int cc = 0; cc < 8; cc++) acc[rr][cc] += av[rr] * bv[cc];
        }
        __syncthreads();
    }
}

// ---------------- QKV GEMM (z = 0/1/2 selects weight); z==2 also fills out_v
__global__ void __launch_bounds__(256, 2) qkv_gemm(const float* __restrict__ x,
                                                   const float* __restrict__ Wq,
                                                   const float* __restrict__ Wk,
                                                   const float* __restrict__ Wv,
                                                   float* __restrict__ out_v) {
    __shared__ float As[16 * 132];
    __shared__ float Bs[16 * 132];
    const int i0 = blockIdx.y * 128;
    const int j0 = blockIdx.x * 128;
    const int z = blockIdx.z;
    const float* Bw = (z == 0) ? Wq : (z == 1) ? Wk : Wv;

    float acc[8][8] = {};
    sgemm_tile(x, Bw, i0, j0, As, Bs, acc);

    const int tx = threadIdx.x & 15;
    const int ty = threadIdx.x >> 4;
#pragma unroll
    for (int rr = 0; rr < 8; rr++) {
        const int grow = i0 + ty * 8 + rr;
        float* crow = g_qkv + (size_t)grow * (3 * C_) + z * C_ + j0 + tx * 8;
        *(float4*)crow = make_float4(acc[rr][0], acc[rr][1], acc[rr][2], acc[rr][3]);
        *(float4*)(crow + 4) = make_float4(acc[rr][4], acc[rr][5], acc[rr][6], acc[rr][7]);
        if (z == 2) {
            const int b = grow / N_;
            const int n = grow % N_;
#pragma unroll
            for (int cc = 0; cc < 8; cc++) {
                const int col = j0 + tx * 8 + cc;
                const int h = col / D_;
                const int dd = col % D_;
                out_v[((size_t)(b * H_ + h) * N_ + n) * D_ + dd] = acc[rr][cc];
            }
        }
    }
}

// ---------------- projection GEMM: out = g_o @ Wproj^T + b ------------------
__global__ void __launch_bounds__(256, 2) proj_gemm(const float* __restrict__ Wp,
                                                    const float* __restrict__ bias,
                                                    float* __restrict__ Cmat) {
    __shared__ float As[16 * 132];
    __shared__ float Bs[16 * 132];
    const int i0 = blockIdx.y * 128;
    const int j0 = blockIdx.x * 128;

    float acc[8][8] = {};
    sgemm_tile(g_o, Wp, i0, j0, As, Bs, acc);

    const int tx = threadIdx.x & 15;
    const int ty = threadIdx.x >> 4;
    float bv0[8];
#pragma unroll
    for (int cc = 0; cc < 8; cc++) bv0[cc] = bias[j0 + tx * 8 + cc];
#pragma unroll
    for (int rr = 0; rr < 8; rr++) {
        float* crow = Cmat + (size_t)(i0 + ty * 8 + rr) * C_ + j0 + tx * 8;
        *(float4*)crow = make_float4(acc[rr][0] + bv0[0], acc[rr][1] + bv0[1],
                                     acc[rr][2] + bv0[2], acc[rr][3] + bv0[3]);
        *(float4*)(crow + 4) = make_float4(acc[rr][4] + bv0[4], acc[rr][5] + bv0[5],
                                           acc[rr][6] + bv0[6], acc[rr][7] + bv0[7]);
    }
}

// ---------------- positional scores: softmax over m of (rel . W_pos + b) ---
__global__ void __launch_bounds__(256) pos_kernel(const float* __restrict__ W_pos,
                                                  const float* __restrict__ b_pos) {
    const int n = blockIdx.x;
    const int h = blockIdx.y;
    const int i1 = n / S_;
    const int j1 = n % S_;
    const float w0 = W_pos[h * 3 + 0];
    const float w1 = W_pos[h * 3 + 1];
    const float w2 = W_pos[h * 3 + 2];
    const float bp = b_pos[h];

    __shared__ float buf[N_];
    __shared__ float red[256];
    const int tid = threadIdx.x;

    float lmax = -1e30f;
    for (int m = tid; m < N_; m += 256) {
        float dx = (float)(m % S_ - j1);
        float dy = (float)(m / S_ - i1);
        float l = w0 * dx + w1 * dy + w2 * (dx * dx + dy * dy) + bp;
        buf[m] = l;
        lmax = fmaxf(lmax, l);
    }
    red[tid] = lmax;
    __syncthreads();
    for (int s = 128; s > 0; s >>= 1) {
        if (tid < s) red[tid] = fmaxf(red[tid], red[tid + s]);
        __syncthreads();
    }
    const float mx = red[0];
    __syncthreads();

    float lsum = 0.f;
    for (int m = tid; m < N_; m += 256) {
        float e = __expf(buf[m] - mx);
        buf[m] = e;
        lsum += e;
    }
    red[tid] = lsum;
    __syncthreads();
    for (int s = 128; s > 0; s >>= 1) {
        if (tid < s) red[tid] += red[tid + s];
        __syncthreads();
    }
    const float inv = 1.f / red[0];
    __syncthreads();

    float* row = g_pos + ((size_t)h * N_ + n) * N_;
    for (int m = tid; m < N_; m += 256) row[m] = buf[m] * inv;
}

// ---------------- attention scores (QK^T + dual softmax + gate + renorm) ---
// block = (ntile, h, b); 16 rows; 256 threads (tx=16, ty=16).
// Thread (ty,tx) owns row n0+ty, columns m = c*112 + u*16 + tx (c<7,u<7).
#define CHUNK 112
#define KPAD 52

__global__ void __launch_bounds__(256, 2) attn_scores(const float* __restrict__ gating,
                                                      float* __restrict__ attn_out) {
    const int ntile = blockIdx.x;
    const int h = blockIdx.y;
    const int b = blockIdx.z;
    const int tx = threadIdx.x;
    const int ty = threadIdx.y;
    const int tid = ty * 16 + tx;
    const int n = ntile * 16 + ty;

    __shared__ float Ks[CHUNK][KPAD];

    // ---- Q row into registers, pre-scaled
    float q[D_];
    {
        const float* qrow = g_qkv + (size_t)(b * N_ + n) * (3 * C_) + h * D_;
#pragma unroll
        for (int t = 0; t < 12; t++) {
            float4 v4 = *(const float4*)(qrow + 4 * t);
            q[4 * t + 0] = v4.x * SCALE_;
            q[4 * t + 1] = v4.y * SCALE_;
            q[4 * t + 2] = v4.z * SCALE_;
            q[4 * t + 3] = v4.w * SCALE_;
        }
    }

    float s[49];

    // ---- scores
    for (int c = 0; c < 7; c++) {
        const int m0 = c * CHUNK;
        __syncthreads();
        for (int idx = tid; idx < CHUNK * 12; idx += 256) {
            int row = idx / 12;
            int c4 = idx % 12;
            float4 v4 = *(const float4*)(g_qkv + (size_t)(b * N_ + m0 + row) * (3 * C_) +
                                         C_ + h * D_ + c4 * 4);
            *(float4*)&Ks[row][c4 * 4] = v4;
        }
        __syncthreads();
#pragma unroll
        for (int u = 0; u < 7; u++) {
            const int krow = u * 16 + tx;
            float acc = 0.f;
#pragma unroll
            for (int t = 0; t < 12; t++) {
                float4 kv = *(const float4*)&Ks[krow][4 * t];
                acc += q[4 * t + 0] * kv.x;
                acc += q[4 * t + 1] * kv.y;
                acc += q[4 * t + 2] * kv.z;
                acc += q[4 * t + 3] * kv.w;
            }
            s[c * 7 + u] = acc;
        }
    }

    // ---- patch softmax (reduce across the 16 tx lanes)
    float mx = -1e30f;
#pragma unroll
    for (int j = 0; j < 49; j++) mx = fmaxf(mx, s[j]);
#pragma unroll
    for (int off = 8; off > 0; off >>= 1)
        mx = fmaxf(mx, __shfl_xor_sync(0xffffffffu, mx, off));

    float esum = 0.f;
#pragma unroll
    for (int j = 0; j < 49; j++) {
        s[j] = __expf(s[j] - mx);
        esum += s[j];
    }
#pragma unroll
    for (int off = 8; off > 0; off >>= 1)
        esum += __shfl_xor_sync(0xffffffffu, esum, off);
    const float pinv = 1.f / esum;

    // ---- gate-combine with positional scores, renormalize
    const float gt = gating[h];
    const float g = 1.f / (1.f + __expf(-gt));
    const float* prow = g_pos + ((size_t)h * N_ + n) * N_;
    float asum = 0.f;
#pragma unroll
    for (int j = 0; j < 49; j++) {
        const int m = (j / 7) * CHUNK + (j % 7) * 16 + tx;
        float a = (1.f - g) * (s[j] * pinv) + g * prow[m];
        s[j] = a;
        asum += a;
    }
#pragma unroll
    for (int off = 8; off > 0; off >>= 1)
        asum += __shfl_xor_sync(0xffffffffu, asum, off);
    const float ainv = 1.f / asum;

    float* arow = attn_out + ((size_t)(b * H_ + h) * N_ + n) * N_;
#pragma unroll
    for (int j = 0; j < 49; j++) {
        const int m = (j / 7) * CHUNK + (j % 7) * 16 + tx;
        arow[m] = s[j] * ainv;
    }
}

// ---------------- AV batched GEMM: g_o[bn, h*48+d] = attn[bh] @ V[bh] -------
// block: 112 rows x 48 cols, 128 threads; thread = (ty 0..15, tx 0..7),
// rows ty+16i (i<7), cols tx*6..+5. K chunks of 28.
#define AVKC 28

__global__ void __launch_bounds__(128) av_gemm(const float* __restrict__ attn) {
    __shared__ float Aat[AVKC][116];   // [k][row]
    __shared__ float Vs[AVKC][52];     // [k][d]

    const int bh = blockIdx.y;
    const int b = bh >> 4;
    const int h = bh & 15;
    const int r0 = blockIdx.x * 112;
    const int tid = threadIdx.x;
    const int tx = tid & 7;
    const int ty = tid >> 3;

    const float* abase = attn + (size_t)bh * N_ * N_;
    float acc[7][6] = {};

    for (int k0 = 0; k0 < N_; k0 += AVKC) {
        __syncthreads();
        for (int idx = tid; idx < 112 * 7; idx += 128) {
            const int row = idx / 7;
            const int f4 = idx % 7;
            float4 v = *(const float4*)(abase + (size_t)(r0 + row) * N_ + k0 + f4 * 4);
            Aat[f4 * 4 + 0][row] = v.x;
            Aat[f4 * 4 + 1][row] = v.y;
            Aat[f4 * 4 + 2][row] = v.z;
            Aat[f4 * 4 + 3][row] = v.w;
        }
        for (int idx = tid; idx < AVKC * 12; idx += 128) {
            const int kk = idx / 12;
            const int c4 = idx % 12;
            float4 v = *(const float4*)(g_qkv + (size_t)(b * N_ + k0 + kk) * (3 * C_) +
                                        2 * C_ + h * D_ + c4 * 4);
            *(float4*)&Vs[kk][c4 * 4] = v;
        }
        __syncthreads();
#pragma unroll 4
        for (int kk = 0; kk < AVKC; kk++) {
            float a[7], bb[6];
#pragma unroll
            for (int i = 0; i < 7; i++) a[i] = Aat[kk][ty + 16 * i];
#pragma unroll
            for (int j = 0; j < 6; j++) bb[j] = Vs[kk][tx * 6 + j];
#pragma unroll
            for (int i = 0; i < 7; i++)
#pragma unroll
                for (int j = 0; j < 6; j++) acc[i][j] += a[i] * bb[j];
        }
    }

#pragma unroll
    for (int i = 0; i < 7; i++) {
        const int nrow = r0 + ty + 16 * i;
        float* orow = g_o + (size_t)(b * N_ + nrow) * C_ + h * D_ + tx * 6;
#pragma unroll
        for (int j = 0; j < 6; j++) orow[j] = acc[i][j];
    }
}

// ---------------- launch ----------------------------------------------------
extern "C" void kernel_launch(void* const* d_in, const int* in_sizes, int n_in,
                              void* d_out, int out_size) {
    const float* x      = (const float*)d_in[0];
    const float* Wq     = (const float*)d_in[1];
    const float* Wk     = (const float*)d_in[2];
    const float* Wv     = (const float*)d_in[3];
    const float* Wproj  = (const float*)d_in[4];
    const float* b_proj = (const float*)d_in[5];
    const float* W_pos  = (const float*)d_in[6];
    const float* b_pos  = (const float*)d_in[7];
    const float* gating = (const float*)d_in[8];

    float* out_o    = (float*)d_out;                              // [B,N,C]
    float* out_attn = out_o + (size_t)B_ * N_ * C_;               // [B,H,N,N]
    float* out_v    = out_attn + (size_t)B_ * H_ * N_ * N_;       // [B,H,N,D]

    qkv_gemm<<<dim3(C_ / 128, M_ / 128, 3), 256>>>(x, Wq, Wk, Wv, out_v);

    pos_kernel<<<dim3(N_, H_), 256>>>(W_pos, b_pos);

    attn_scores<<<dim3(N_ / 16, H_, B_), dim3(16, 16)>>>(gating, out_attn);

    av_gemm<<<dim3(N_ / 112, B_ * H_), 128>>>(out_attn);

    proj_gemm<<<dim3(C_ / 128, M_ / 128), 256>>>(Wproj, b_proj, out_o);
}

// round 5
// speedup vs baseline: 2.1416x; 1.6927x over previous
#include <cuda_runtime.h>
#include <cuda_bf16.h>
#include <mma.h>
#include <cstddef>
#include <cstdint>

using namespace nvcuda;

// Problem constants
#define B_ 8
#define N_ 784
#define C_ 768
#define H_ 16
#define D_ 48
#define S_ 28
#define M_ (B_ * N_)          // 6272 rows
#define SCALE_ 0.14433756729740643f  // 48^-0.5

// ---------------- scratch (device globals; no allocation allowed) ----------
__device__ float g_qkv[(size_t)M_ * 3 * C_];   // [M, 3C] : q | k | v
__device__ float g_pos[(size_t)H_ * N_ * N_];  // softmaxed positional scores
__device__ float g_o[(size_t)M_ * C_];         // attention output pre-projection
__device__ __nv_bfloat16 g_xh[(size_t)M_ * C_], g_xl[(size_t)M_ * C_];
__device__ __nv_bfloat16 g_wh[4 * (size_t)C_ * C_], g_wl[4 * (size_t)C_ * C_];
__device__ __nv_bfloat16 g_oh[(size_t)M_ * C_], g_ol[(size_t)M_ * C_];

// ---------------- fp32 -> (hi, lo) bf16 split kernels -----------------------
__device__ __forceinline__ void split4(const float* src, __nv_bfloat16* hi,
                                       __nv_bfloat16* lo, size_t i4) {
    float4 v = *(const float4*)(src + i4 * 4);
    float vs[4] = {v.x, v.y, v.z, v.w};
    __nv_bfloat16 h[4], l[4];
#pragma unroll
    for (int j = 0; j < 4; j++) {
        h[j] = __float2bfloat16(vs[j]);
        l[j] = __float2bfloat16(vs[j] - __bfloat162float(h[j]));
    }
    *(uint2*)(hi + i4 * 4) = *(uint2*)h;
    *(uint2*)(lo + i4 * 4) = *(uint2*)l;
}

__global__ void __launch_bounds__(256) split_x(const float* __restrict__ x) {
    size_t i = (size_t)blockIdx.x * 256 + threadIdx.x;
    if (i < (size_t)M_ * C_ / 4) split4(x, g_xh, g_xl, i);
}
__global__ void __launch_bounds__(256) split_w(const float* __restrict__ Wq,
                                               const float* __restrict__ Wk,
                                               const float* __restrict__ Wv,
                                               const float* __restrict__ Wp) {
    const int z = blockIdx.y;
    const float* src = (z == 0) ? Wq : (z == 1) ? Wk : (z == 2) ? Wv : Wp;
    size_t i = (size_t)blockIdx.x * 256 + threadIdx.x;
    if (i < (size_t)C_ * C_ / 4)
        split4(src, g_wh + (size_t)z * C_ * C_, g_wl + (size_t)z * C_ * C_, i);
}
__global__ void __launch_bounds__(256) split_o() {
    size_t i = (size_t)blockIdx.x * 256 + threadIdx.x;
    if (i < (size_t)M_ * C_ / 4) split4(g_o, g_oh, g_ol, i);
}

// ================= wmma split-bf16 GEMM (128x128 block tile) ================
// C[i,j] = sum_k A[i,k]*B[j,k]  via  Ah*Bh + Ah*Bl + Al*Bh  (fp32 accum)
// 256 threads = 8 warps; warp tile 64x32 (4x2 m16n16k16 tiles); K chunk 32.
#define TSTR 40   // smem tile stride (bf16 elems)

__global__ void __launch_bounds__(256) tc_gemm(int mode, float* __restrict__ outC) {
    __shared__ __nv_bfloat16 sAh[128 * TSTR], sAl[128 * TSTR];
    __shared__ __nv_bfloat16 sBh[128 * TSTR], sBl[128 * TSTR];

    const int tid = threadIdx.x;
    const int w = tid >> 5;
    const int wm = w & 1;          // 0..1  (64 rows each)
    const int wn = w >> 1;         // 0..3  (32 cols each)
    const int j0 = blockIdx.x * 128;
    const int i0 = blockIdx.y * 128;
    const int z = blockIdx.z;

    const __nv_bfloat16 *Ah, *Al, *Bh, *Bl;
    if (mode == 0) {
        Ah = g_xh; Al = g_xl;
        Bh = g_wh + (size_t)z * C_ * C_; Bl = g_wl + (size_t)z * C_ * C_;
    } else {
        Ah = g_oh; Al = g_ol;
        Bh = g_wh + (size_t)3 * C_ * C_; Bl = g_wl + (size_t)3 * C_ * C_;
    }

    wmma::fragment<wmma::accumulator, 16, 16, 16, float> acc[4][2];
#pragma unroll
    for (int i = 0; i < 4; i++)
#pragma unroll
        for (int j = 0; j < 2; j++) wmma::fill_fragment(acc[i][j], 0.f);

    for (int k0 = 0; k0 < C_; k0 += 32) {
        // load 4 tiles of 128x32 bf16 (uint4 = 8 bf16)
#pragma unroll
        for (int it = 0; it < 2; it++) {
            const int v = tid + it * 256;
            const int row = v >> 2;
            const int seg = (v & 3) * 8;
            const size_t sa = (size_t)(i0 + row) * C_ + k0 + seg;
            const size_t sb = (size_t)(j0 + row) * C_ + k0 + seg;
            const int dst = row * TSTR + seg;
            *(uint4*)&sAh[dst] = *(const uint4*)(Ah + sa);
            *(uint4*)&sAl[dst] = *(const uint4*)(Al + sa);
            *(uint4*)&sBh[dst] = *(const uint4*)(Bh + sb);
            *(uint4*)&sBl[dst] = *(const uint4*)(Bl + sb);
        }
        __syncthreads();

#pragma unroll
        for (int ks = 0; ks < 2; ks++) {
            const int kk = ks * 16;
            wmma::fragment<wmma::matrix_a, 16, 16, 16, __nv_bfloat16, wmma::row_major> ah[4], al[4];
            wmma::fragment<wmma::matrix_b, 16, 16, 16, __nv_bfloat16, wmma::col_major> bh[2], bl[2];
#pragma unroll
            for (int i = 0; i < 4; i++) {
                const int r = wm * 64 + i * 16;
                wmma::load_matrix_sync(ah[i], &sAh[r * TSTR + kk], TSTR);
                wmma::load_matrix_sync(al[i], &sAl[r * TSTR + kk], TSTR);
            }
#pragma unroll
            for (int j = 0; j < 2; j++) {
                const int c = wn * 32 + j * 16;
                wmma::load_matrix_sync(bh[j], &sBh[c * TSTR + kk], TSTR);
                wmma::load_matrix_sync(bl[j], &sBl[c * TSTR + kk], TSTR);
            }
#pragma unroll
            for (int i = 0; i < 4; i++)
#pragma unroll
                for (int j = 0; j < 2; j++) {
                    wmma::mma_sync(acc[i][j], ah[i], bh[j], acc[i][j]);
                    wmma::mma_sync(acc[i][j], ah[i], bl[j], acc[i][j]);
                    wmma::mma_sync(acc[i][j], al[i], bh[j], acc[i][j]);
                }
        }
        __syncthreads();
    }

    // epilogue: direct global stores
#pragma unroll
    for (int i = 0; i < 4; i++) {
        const int row = i0 + wm * 64 + i * 16;
#pragma unroll
        for (int j = 0; j < 2; j++) {
            const int col = j0 + wn * 32 + j * 16;
            if (mode == 0) {
                wmma::store_matrix_sync(g_qkv + (size_t)row * (3 * C_) + z * C_ + col,
                                        acc[i][j], 3 * C_, wmma::mem_row_major);
            } else {
                wmma::store_matrix_sync(outC + (size_t)row * C_ + col,
                                        acc[i][j], C_, wmma::mem_row_major);
            }
        }
    }
}

// ---------------- bias add (proj epilogue) ----------------------------------
__global__ void __launch_bounds__(256) bias_add(float* __restrict__ out,
                                                const float* __restrict__ bias) {
    size_t i = (size_t)blockIdx.x * 256 + threadIdx.x;
    if (i < (size_t)M_ * C_ / 4) {
        float4 v = *(float4*)(out + i * 4);
        const int j = (int)((i * 4) % C_);
        v.x += bias[j]; v.y += bias[j + 1]; v.z += bias[j + 2]; v.w += bias[j + 3];
        *(float4*)(out + i * 4) = v;
    }
}

// ---------------- repack V into output region [b,h,n,d] --------------------
__global__ void __launch_bounds__(256) repack_v(float* __restrict__ vout) {
    int idx = blockIdx.x * 256 + threadIdx.x;
    if (idx >= M_ * C_) return;
    int i = idx / C_;
    int j = idx % C_;
    int b = i / N_;
    int n = i % N_;
    int h = j / D_;
    int dd = j % D_;
    vout[((size_t)(b * H_ + h) * N_ + n) * D_ + dd] =
        g_qkv[(size_t)i * (3 * C_) + 2 * C_ + j];
}

// ---------------- positional scores: softmax over m of (rel . W_pos + b) ---
__global__ void __launch_bounds__(256) pos_kernel(const float* __restrict__ W_pos,
                                                  const float* __restrict__ b_pos) {
    const int n = blockIdx.x;
    const int h = blockIdx.y;
    const int i1 = n / S_;
    const int j1 = n % S_;
    const float w0 = W_pos[h * 3 + 0];
    const float w1 = W_pos[h * 3 + 1];
    const float w2 = W_pos[h * 3 + 2];
    const float bp = b_pos[h];

    __shared__ float buf[N_];
    __shared__ float red[256];
    const int tid = threadIdx.x;

    float lmax = -1e30f;
    for (int m = tid; m < N_; m += 256) {
        float dx = (float)(m % S_ - j1);
        float dy = (float)(m / S_ - i1);
        float l = w0 * dx + w1 * dy + w2 * (dx * dx + dy * dy) + bp;
        buf[m] = l;
        lmax = fmaxf(lmax, l);
    }
    red[tid] = lmax;
    __syncthreads();
    for (int s = 128; s > 0; s >>= 1) {
        if (tid < s) red[tid] = fmaxf(red[tid], red[tid + s]);
        __syncthreads();
    }
    const float mx = red[0];
    __syncthreads();

    float lsum = 0.f;
    for (int m = tid; m < N_; m += 256) {
        float e = __expf(buf[m] - mx);
        buf[m] = e;
        lsum += e;
    }
    red[tid] = lsum;
    __syncthreads();
    for (int s = 128; s > 0; s >>= 1) {
        if (tid < s) red[tid] += red[tid + s];
        __syncthreads();
    }
    const float inv = 1.f / red[0];
    __syncthreads();

    float* row = g_pos + ((size_t)h * N_ + n) * N_;
    for (int m = tid; m < N_; m += 256) row[m] = buf[m] * inv;
}

// ---------------- attention scores (QK^T + dual softmax + gate + renorm) ---
#define CHUNK 112
#define KPAD 52

__global__ void __launch_bounds__(256, 2) attn_scores(const float* __restrict__ gating,
                                                      float* __restrict__ attn_out) {
    const int ntile = blockIdx.x;
    const int h = blockIdx.y;
    const int b = blockIdx.z;
    const int tx = threadIdx.x;
    const int ty = threadIdx.y;
    const int tid = ty * 16 + tx;
    const int n = ntile * 16 + ty;

    __shared__ float Ks[CHUNK][KPAD];

    float q[D_];
    {
        const float* qrow = g_qkv + (size_t)(b * N_ + n) * (3 * C_) + h * D_;
#pragma unroll
        for (int t = 0; t < 12; t++) {
            float4 v4 = *(const float4*)(qrow + 4 * t);
            q[4 * t + 0] = v4.x * SCALE_;
            q[4 * t + 1] = v4.y * SCALE_;
            q[4 * t + 2] = v4.z * SCALE_;
            q[4 * t + 3] = v4.w * SCALE_;
        }
    }

    float s[49];

    for (int c = 0; c < 7; c++) {
        const int m0 = c * CHUNK;
        __syncthreads();
        for (int idx = tid; idx < CHUNK * 12; idx += 256) {
            int row = idx / 12;
            int c4 = idx % 12;
            float4 v4 = *(const float4*)(g_qkv + (size_t)(b * N_ + m0 + row) * (3 * C_) +
                                         C_ + h * D_ + c4 * 4);
            *(float4*)&Ks[row][c4 * 4] = v4;
        }
        __syncthreads();
#pragma unroll
        for (int u = 0; u < 7; u++) {
            const int krow = u * 16 + tx;
            float acc = 0.f;
#pragma unroll
            for (int t = 0; t < 12; t++) {
                float4 kv = *(const float4*)&Ks[krow][4 * t];
                acc += q[4 * t + 0] * kv.x;
                acc += q[4 * t + 1] * kv.y;
                acc += q[4 * t + 2] * kv.z;
                acc += q[4 * t + 3] * kv.w;
            }
            s[c * 7 + u] = acc;
        }
    }

    float mx = -1e30f;
#pragma unroll
    for (int j = 0; j < 49; j++) mx = fmaxf(mx, s[j]);
#pragma unroll
    for (int off = 8; off > 0; off >>= 1)
        mx = fmaxf(mx, __shfl_xor_sync(0xffffffffu, mx, off));

    float esum = 0.f;
#pragma unroll
    for (int j = 0; j < 49; j++) {
        s[j] = __expf(s[j] - mx);
        esum += s[j];
    }
#pragma unroll
    for (int off = 8; off > 0; off >>= 1)
        esum += __shfl_xor_sync(0xffffffffu, esum, off);
    const float pinv = 1.f / esum;

    const float gt = gating[h];
    const float g = 1.f / (1.f + __expf(-gt));
    const float* prow = g_pos + ((size_t)h * N_ + n) * N_;
    float asum = 0.f;
#pragma unroll
    for (int j = 0; j < 49; j++) {
        const int m = (j / 7) * CHUNK + (j % 7) * 16 + tx;
        float a = (1.f - g) * (s[j] * pinv) + g * prow[m];
        s[j] = a;
        asum += a;
    }
#pragma unroll
    for (int off = 8; off > 0; off >>= 1)
        asum += __shfl_xor_sync(0xffffffffu, asum, off);
    const float ainv = 1.f / asum;

    float* arow = attn_out + ((size_t)(b * H_ + h) * N_ + n) * N_;
#pragma unroll
    for (int j = 0; j < 49; j++) {
        const int m = (j / 7) * CHUNK + (j % 7) * 16 + tx;
        arow[m] = s[j] * ainv;
    }
}

// ---------------- AV batched GEMM: g_o[bn, h*48+d] = attn[bh] @ V[bh] -------
// 128 rows x 48 cols per block, 192 threads, 8x4 microtile, K chunks of 28.
#define AVKC 28

__global__ void __launch_bounds__(192) av_gemm(const float* __restrict__ attn) {
    __shared__ float Aat[AVKC][132];   // [k][row]
    __shared__ float Vs[AVKC][52];     // [k][d]

    const int bh = blockIdx.y;
    const int b = bh >> 4;
    const int h = bh & 15;
    const int r0 = blockIdx.x * 128;
    const int tid = threadIdx.x;
    const int tx = tid % 12;           // col group (4 cols)
    const int ty = tid / 12;           // row group (8 rows)

    const float* abase = attn + (size_t)bh * N_ * N_;
    float acc[8][4] = {};

    for (int k0 = 0; k0 < N_; k0 += AVKC) {
        __syncthreads();
        for (int idx = tid; idx < 128 * 7; idx += 192) {
            const int row = idx / 7;
            const int f4 = idx % 7;
            const int gr = r0 + row;
            float4 v = (gr < N_) ? *(const float4*)(abase + (size_t)gr * N_ + k0 + f4 * 4)
                                 : make_float4(0.f, 0.f, 0.f, 0.f);
            Aat[f4 * 4 + 0][row] = v.x;
            Aat[f4 * 4 + 1][row] = v.y;
            Aat[f4 * 4 + 2][row] = v.z;
            Aat[f4 * 4 + 3][row] = v.w;
        }
        for (int idx = tid; idx < AVKC * 12; idx += 192) {
            const int kk = idx / 12;
            const int c4 = idx % 12;
            *(float4*)&Vs[kk][c4 * 4] =
                *(const float4*)(g_qkv + (size_t)(b * N_ + k0 + kk) * (3 * C_) +
                                 2 * C_ + h * D_ + c4 * 4);
        }
        __syncthreads();
#pragma unroll 4
        for (int kk = 0; kk < AVKC; kk++) {
            float4 a0 = *(const float4*)&Aat[kk][ty * 8];
            float4 a1 = *(const float4*)&Aat[kk][ty * 8 + 4];
            float4 bv = *(const float4*)&Vs[kk][tx * 4];
            float a[8] = {a0.x, a0.y, a0.z, a0.w, a1.x, a1.y, a1.z, a1.w};
            float bb[4] = {bv.x, bv.y, bv.z, bv.w};
#pragma unroll
            for (int i = 0; i < 8; i++)
#pragma unroll
                for (int j = 0; j < 4; j++) acc[i][j] += a[i] * bb[j];
        }
    }

#pragma unroll
    for (int i = 0; i < 8; i++) {
        const int n = r0 + ty * 8 + i;
        if (n < N_)
            *(float4*)(g_o + (size_t)(b * N_ + n) * C_ + h * D_ + tx * 4) =
                make_float4(acc[i][0], acc[i][1], acc[i][2], acc[i][3]);
    }
}

// ---------------- launch ----------------------------------------------------
extern "C" void kernel_launch(void* const* d_in, const int* in_sizes, int n_in,
                              void* d_out, int out_size) {
    const float* x      = (const float*)d_in[0];
    const float* Wq     = (const float*)d_in[1];
    const float* Wk     = (const float*)d_in[2];
    const float* Wv     = (const float*)d_in[3];
    const float* Wproj  = (const float*)d_in[4];
    const float* b_proj = (const float*)d_in[5];
    const float* W_pos  = (const float*)d_in[6];
    const float* b_pos  = (const float*)d_in[7];
    const float* gating = (const float*)d_in[8];

    float* out_o    = (float*)d_out;                              // [B,N,C]
    float* out_attn = out_o + (size_t)B_ * N_ * C_;               // [B,H,N,N]
    float* out_v    = out_attn + (size_t)B_ * H_ * N_ * N_;       // [B,H,N,D]

    split_x<<<(M_ * C_ / 4 + 255) / 256, 256>>>(x);
    split_w<<<dim3((C_ * C_ / 4 + 255) / 256, 4), 256>>>(Wq, Wk, Wv, Wproj);

    tc_gemm<<<dim3(C_ / 128, M_ / 128, 3), 256>>>(0, nullptr);

    pos_kernel<<<dim3(N_, H_), 256>>>(W_pos, b_pos);

    repack_v<<<(M_ * C_ + 255) / 256, 256>>>(out_v);

    attn_scores<<<dim3(N_ / 16, H_, B_), dim3(16, 16)>>>(gating, out_attn);

    av_gemm<<<dim3((N_ + 127) / 128, B_ * H_), 192>>>(out_attn);

    split_o<<<(M_ * C_ / 4 + 255) / 256, 256>>>();

    tc_gemm<<<dim3(C_ / 128, M_ / 128, 1), 256>>>(1, out_o);

    bias_add<<<(M_ * C_ / 4 + 255) / 256, 256>>>(out_o, b_proj);
}

// round 6
// speedup vs baseline: 2.6592x; 1.2417x over previous
#include <cuda_runtime.h>
#include <cuda_bf16.h>
#include <mma.h>
#include <cstddef>
#include <cstdint>

using namespace nvcuda;

// Problem constants
#define B_ 8
#define N_ 784
#define C_ 768
#define H_ 16
#define D_ 48
#define S_ 28
#define M_ (B_ * N_)          // 6272 rows
#define BH_ (B_ * H_)         // 128
#define SCALE_ 0.14433756729740643f  // 48^-0.5

// ---------------- scratch (device globals; no allocation allowed) ----------
__device__ float g_pos[(size_t)H_ * N_ * N_];  // softmaxed positional scores
__device__ float g_o[(size_t)M_ * C_];         // attention output pre-projection
__device__ __nv_bfloat16 g_xh[(size_t)M_ * C_], g_xl[(size_t)M_ * C_];
__device__ __nv_bfloat16 g_wh[4 * (size_t)C_ * C_], g_wl[4 * (size_t)C_ * C_];
__device__ __nv_bfloat16 g_oh[(size_t)M_ * C_], g_ol[(size_t)M_ * C_];
// per-head split operands: [bh][n][48]
__device__ __nv_bfloat16 g_qh[(size_t)BH_ * N_ * D_], g_ql[(size_t)BH_ * N_ * D_];
__device__ __nv_bfloat16 g_kh[(size_t)BH_ * N_ * D_], g_kl[(size_t)BH_ * N_ * D_];
__device__ __nv_bfloat16 g_vh[(size_t)BH_ * N_ * D_], g_vl[(size_t)BH_ * N_ * D_];

// ---------------- fp32 -> (hi, lo) bf16 split kernels -----------------------
__device__ __forceinline__ void split4(const float* src, __nv_bfloat16* hi,
                                       __nv_bfloat16* lo, size_t i4) {
    float4 v = *(const float4*)(src + i4 * 4);
    float vs[4] = {v.x, v.y, v.z, v.w};
    __nv_bfloat16 h[4], l[4];
#pragma unroll
    for (int j = 0; j < 4; j++) {
        h[j] = __float2bfloat16(vs[j]);
        l[j] = __float2bfloat16(vs[j] - __bfloat162float(h[j]));
    }
    *(uint2*)(hi + i4 * 4) = *(uint2*)h;
    *(uint2*)(lo + i4 * 4) = *(uint2*)l;
}

__global__ void __launch_bounds__(256) split_x(const float* __restrict__ x) {
    size_t i = (size_t)blockIdx.x * 256 + threadIdx.x;
    if (i < (size_t)M_ * C_ / 4) split4(x, g_xh, g_xl, i);
}
__global__ void __launch_bounds__(256) split_w(const float* __restrict__ Wq,
                                               const float* __restrict__ Wk,
                                               const float* __restrict__ Wv,
                                               const float* __restrict__ Wp) {
    const int z = blockIdx.y;
    const float* src = (z == 0) ? Wq : (z == 1) ? Wk : (z == 2) ? Wv : Wp;
    size_t i = (size_t)blockIdx.x * 256 + threadIdx.x;
    if (i < (size_t)C_ * C_ / 4)
        split4(src, g_wh + (size_t)z * C_ * C_, g_wl + (size_t)z * C_ * C_, i);
}
__global__ void __launch_bounds__(256) split_o() {
    size_t i = (size_t)blockIdx.x * 256 + threadIdx.x;
    if (i < (size_t)M_ * C_ / 4) split4(g_o, g_oh, g_ol, i);
}

// ================= wmma split-bf16 GEMM (128x128 block tile) ================
// C[i,j] = sum_k A[i,k]*B[j,k]  via  Ah*Bh + Ah*Bl + Al*Bh  (fp32 accum)
// mode 0: qkv — epilogue scatters into qh/ql | kh/kl | out_v + vh/vl
// mode 1: proj — direct store to outC
#define TSTR 40   // smem tile stride (bf16 elems)

__global__ void __launch_bounds__(256) tc_gemm(int mode, float* __restrict__ outC,
                                               float* __restrict__ out_v) {
    __shared__ __nv_bfloat16 sAh[128 * TSTR], sAl[128 * TSTR];
    __shared__ __nv_bfloat16 sBh[128 * TSTR], sBl[128 * TSTR];
    __shared__ float stage[8][256];

    const int tid = threadIdx.x;
    const int w = tid >> 5;
    const int lid = tid & 31;
    const int wm = w & 1;          // 0..1  (64 rows each)
    const int wn = w >> 1;         // 0..3  (32 cols each)
    const int j0 = blockIdx.x * 128;
    const int i0 = blockIdx.y * 128;
    const int z = blockIdx.z;

    const __nv_bfloat16 *Ah, *Al, *Bh, *Bl;
    if (mode == 0) {
        Ah = g_xh; Al = g_xl;
        Bh = g_wh + (size_t)z * C_ * C_; Bl = g_wl + (size_t)z * C_ * C_;
    } else {
        Ah = g_oh; Al = g_ol;
        Bh = g_wh + (size_t)3 * C_ * C_; Bl = g_wl + (size_t)3 * C_ * C_;
    }

    wmma::fragment<wmma::accumulator, 16, 16, 16, float> acc[4][2];
#pragma unroll
    for (int i = 0; i < 4; i++)
#pragma unroll
        for (int j = 0; j < 2; j++) wmma::fill_fragment(acc[i][j], 0.f);

    for (int k0 = 0; k0 < C_; k0 += 32) {
#pragma unroll
        for (int it = 0; it < 2; it++) {
            const int v = tid + it * 256;
            const int row = v >> 2;
            const int seg = (v & 3) * 8;
            const size_t sa = (size_t)(i0 + row) * C_ + k0 + seg;
            const size_t sb = (size_t)(j0 + row) * C_ + k0 + seg;
            const int dst = row * TSTR + seg;
            *(uint4*)&sAh[dst] = *(const uint4*)(Ah + sa);
            *(uint4*)&sAl[dst] = *(const uint4*)(Al + sa);
            *(uint4*)&sBh[dst] = *(const uint4*)(Bh + sb);
            *(uint4*)&sBl[dst] = *(const uint4*)(Bl + sb);
        }
        __syncthreads();

#pragma unroll
        for (int ks = 0; ks < 2; ks++) {
            const int kk = ks * 16;
            wmma::fragment<wmma::matrix_a, 16, 16, 16, __nv_bfloat16, wmma::row_major> fah[4], fal[4];
            wmma::fragment<wmma::matrix_b, 16, 16, 16, __nv_bfloat16, wmma::col_major> fbh[2], fbl[2];
#pragma unroll
            for (int i = 0; i < 4; i++) {
                const int r = wm * 64 + i * 16;
                wmma::load_matrix_sync(fah[i], &sAh[r * TSTR + kk], TSTR);
                wmma::load_matrix_sync(fal[i], &sAl[r * TSTR + kk], TSTR);
            }
#pragma unroll
            for (int j = 0; j < 2; j++) {
                const int c = wn * 32 + j * 16;
                wmma::load_matrix_sync(fbh[j], &sBh[c * TSTR + kk], TSTR);
                wmma::load_matrix_sync(fbl[j], &sBl[c * TSTR + kk], TSTR);
            }
#pragma unroll
            for (int i = 0; i < 4; i++)
#pragma unroll
                for (int j = 0; j < 2; j++) {
                    wmma::mma_sync(acc[i][j], fah[i], fbh[j], acc[i][j]);
                    wmma::mma_sync(acc[i][j], fah[i], fbl[j], acc[i][j]);
                    wmma::mma_sync(acc[i][j], fal[i], fbh[j], acc[i][j]);
                }
        }
        __syncthreads();
    }

    if (mode == 1) {
#pragma unroll
        for (int i = 0; i < 4; i++) {
            const int row = i0 + wm * 64 + i * 16;
#pragma unroll
            for (int j = 0; j < 2; j++) {
                const int col = j0 + wn * 32 + j * 16;
                wmma::store_matrix_sync(outC + (size_t)row * C_ + col,
                                        acc[i][j], C_, wmma::mem_row_major);
            }
        }
        return;
    }

    // mode 0 epilogue: stage each fragment, scatter to per-head split buffers
#pragma unroll
    for (int i = 0; i < 4; i++) {
        const int row0 = i0 + wm * 64 + i * 16;
#pragma unroll
        for (int j = 0; j < 2; j++) {
            const int col0 = j0 + wn * 32 + j * 16;
            __syncwarp();
            wmma::store_matrix_sync(&stage[w][0], acc[i][j], 16, wmma::mem_row_major);
            __syncwarp();
#pragma unroll
            for (int tt = 0; tt < 8; tt++) {
                const int idx = tt * 32 + lid;
                float v = stage[w][idx];
                const int grow = row0 + (idx >> 4);
                const int gcol = col0 + (idx & 15);
                const int b = grow / N_;
                const int n = grow % N_;
                const int h = gcol / D_;
                const int d = gcol % D_;
                const size_t dst = ((size_t)(b * H_ + h) * N_ + n) * D_ + d;
                if (z == 0) {
                    v *= SCALE_;
                    __nv_bfloat16 hi = __float2bfloat16(v);
                    g_qh[dst] = hi;
                    g_ql[dst] = __float2bfloat16(v - __bfloat162float(hi));
                } else if (z == 1) {
                    __nv_bfloat16 hi = __float2bfloat16(v);
                    g_kh[dst] = hi;
                    g_kl[dst] = __float2bfloat16(v - __bfloat162float(hi));
                } else {
                    out_v[dst] = v;
                    __nv_bfloat16 hi = __float2bfloat16(v);
                    g_vh[dst] = hi;
                    g_vl[dst] = __float2bfloat16(v - __bfloat162float(hi));
                }
            }
        }
    }
}

// ---------------- bias add (proj epilogue) ----------------------------------
__global__ void __launch_bounds__(256) bias_add(float* __restrict__ out,
                                                const float* __restrict__ bias) {
    size_t i = (size_t)blockIdx.x * 256 + threadIdx.x;
    if (i < (size_t)M_ * C_ / 4) {
        float4 v = *(float4*)(out + i * 4);
        const int j = (int)((i * 4) % C_);
        v.x += bias[j]; v.y += bias[j + 1]; v.z += bias[j + 2]; v.w += bias[j + 3];
        *(float4*)(out + i * 4) = v;
    }
}

// ================ QK^T wmma GEMM: raw scores into attn buffer ===============
// per bh: S[n,m] = q[n,:].k[m,:] (scale pre-folded into q). 128x128 tiles.
#define QSTR 48

__global__ void __launch_bounds__(256) qk_gemm(float* __restrict__ attn) {
    __shared__ __nv_bfloat16 sQh[128 * QSTR], sQl[128 * QSTR];
    __shared__ __nv_bfloat16 sKh[128 * QSTR], sKl[128 * QSTR];

    const int tid = threadIdx.x;
    const int w = tid >> 5;
    const int wm = w & 1;
    const int wn = w >> 1;
    const int m0 = blockIdx.x * 128;
    const int n0 = blockIdx.y * 128;
    const int bh = blockIdx.z;

    const __nv_bfloat16* qb = g_qh + (size_t)bh * N_ * D_;
    const __nv_bfloat16* qlb = g_ql + (size_t)bh * N_ * D_;
    const __nv_bfloat16* kb = g_kh + (size_t)bh * N_ * D_;
    const __nv_bfloat16* klb = g_kl + (size_t)bh * N_ * D_;

    // load 128x48 tiles (clamp OOB rows)
#pragma unroll
    for (int it = 0; it < 3; it++) {
        const int v = tid + it * 256;
        const int row = v / 6;
        const int seg = (v % 6) * 8;
        const int qrow = min(n0 + row, N_ - 1);
        const int krow = min(m0 + row, N_ - 1);
        const int dst = row * QSTR + seg;
        *(uint4*)&sQh[dst] = *(const uint4*)(qb + (size_t)qrow * D_ + seg);
        *(uint4*)&sQl[dst] = *(const uint4*)(qlb + (size_t)qrow * D_ + seg);
        *(uint4*)&sKh[dst] = *(const uint4*)(kb + (size_t)krow * D_ + seg);
        *(uint4*)&sKl[dst] = *(const uint4*)(klb + (size_t)krow * D_ + seg);
    }
    __syncthreads();

    wmma::fragment<wmma::accumulator, 16, 16, 16, float> acc[4][2];
#pragma unroll
    for (int i = 0; i < 4; i++)
#pragma unroll
        for (int j = 0; j < 2; j++) wmma::fill_fragment(acc[i][j], 0.f);

#pragma unroll
    for (int ks = 0; ks < 3; ks++) {
        const int kk = ks * 16;
        wmma::fragment<wmma::matrix_a, 16, 16, 16, __nv_bfloat16, wmma::row_major> fah[4], fal[4];
        wmma::fragment<wmma::matrix_b, 16, 16, 16, __nv_bfloat16, wmma::col_major> fbh[2], fbl[2];
#pragma unroll
        for (int i = 0; i < 4; i++) {
            const int r = wm * 64 + i * 16;
            wmma::load_matrix_sync(fah[i], &sQh[r * QSTR + kk], QSTR);
            wmma::load_matrix_sync(fal[i], &sQl[r * QSTR + kk], QSTR);
        }
#pragma unroll
        for (int j = 0; j < 2; j++) {
            const int c = wn * 32 + j * 16;
            wmma::load_matrix_sync(fbh[j], &sKh[c * QSTR + kk], QSTR);
            wmma::load_matrix_sync(fbl[j], &sKl[c * QSTR + kk], QSTR);
        }
#pragma unroll
        for (int i = 0; i < 4; i++)
#pragma unroll
            for (int j = 0; j < 2; j++) {
                wmma::mma_sync(acc[i][j], fah[i], fbh[j], acc[i][j]);
                wmma::mma_sync(acc[i][j], fah[i], fbl[j], acc[i][j]);
                wmma::mma_sync(acc[i][j], fal[i], fbh[j], acc[i][j]);
            }
    }

    float* abase = attn + (size_t)bh * N_ * N_;
#pragma unroll
    for (int i = 0; i < 4; i++) {
        const int row = n0 + wm * 64 + i * 16;
        if (row >= N_) continue;
#pragma unroll
        for (int j = 0; j < 2; j++) {
            const int col = m0 + wn * 32 + j * 16;
            if (col >= N_) continue;
            wmma::store_matrix_sync(abase + (size_t)row * N_ + col,
                                    acc[i][j], N_, wmma::mem_row_major);
        }
    }
}

// ---------------- positional scores: softmax over m of (rel . W_pos + b) ---
__global__ void __launch_bounds__(256) pos_kernel(const float* __restrict__ W_pos,
                                                  const float* __restrict__ b_pos) {
    const int n = blockIdx.x;
    const int h = blockIdx.y;
    const int i1 = n / S_;
    const int j1 = n % S_;
    const float w0 = W_pos[h * 3 + 0];
    const float w1 = W_pos[h * 3 + 1];
    const float w2 = W_pos[h * 3 + 2];
    const float bp = b_pos[h];

    __shared__ float buf[N_];
    __shared__ float red[256];
    const int tid = threadIdx.x;

    float lmax = -1e30f;
    for (int m = tid; m < N_; m += 256) {
        float dx = (float)(m % S_ - j1);
        float dy = (float)(m / S_ - i1);
        float l = w0 * dx + w1 * dy + w2 * (dx * dx + dy * dy) + bp;
        buf[m] = l;
        lmax = fmaxf(lmax, l);
    }
    red[tid] = lmax;
    __syncthreads();
    for (int s = 128; s > 0; s >>= 1) {
        if (tid < s) red[tid] = fmaxf(red[tid], red[tid + s]);
        __syncthreads();
    }
    const float mx = red[0];
    __syncthreads();

    float lsum = 0.f;
    for (int m = tid; m < N_; m += 256) {
        float e = __expf(buf[m] - mx);
        buf[m] = e;
        lsum += e;
    }
    red[tid] = lsum;
    __syncthreads();
    for (int s = 128; s > 0; s >>= 1) {
        if (tid < s) red[tid] += red[tid + s];
        __syncthreads();
    }
    const float inv = 1.f / red[0];
    __syncthreads();

    float* row = g_pos + ((size_t)h * N_ + n) * N_;
    for (int m = tid; m < N_; m += 256) row[m] = buf[m] * inv;
}

// ---------- softmax + gate + renorm (in place on raw scores) ----------------
__global__ void __launch_bounds__(256) softmax_gate(const float* __restrict__ gating,
                                                    float* __restrict__ attn) {
    const int n = blockIdx.x;
    const int bh = blockIdx.y;
    const int h = bh & 15;
    const int tid = threadIdx.x;

    __shared__ float buf[N_];
    __shared__ float red[256];

    float* row = attn + ((size_t)bh * N_ + n) * N_;
    const float* prow = g_pos + ((size_t)h * N_ + n) * N_;

    float lmax = -1e30f;
    for (int m = tid; m < N_; m += 256) {
        float v = row[m];
        buf[m] = v;
        lmax = fmaxf(lmax, v);
    }
    red[tid] = lmax;
    __syncthreads();
    for (int s = 128; s > 0; s >>= 1) {
        if (tid < s) red[tid] = fmaxf(red[tid], red[tid + s]);
        __syncthreads();
    }
    const float mx = red[0];
    __syncthreads();

    float lsum = 0.f;
    for (int m = tid; m < N_; m += 256) {
        float e = __expf(buf[m] - mx);
        buf[m] = e;
        lsum += e;
    }
    red[tid] = lsum;
    __syncthreads();
    for (int s = 128; s > 0; s >>= 1) {
        if (tid < s) red[tid] += red[tid + s];
        __syncthreads();
    }
    const float pinv = 1.f / red[0];
    __syncthreads();

    const float g = 1.f / (1.f + __expf(-gating[h]));
    float asum = 0.f;
    for (int m = tid; m < N_; m += 256) {
        float a = (1.f - g) * (buf[m] * pinv) + g * prow[m];
        buf[m] = a;
        asum += a;
    }
    red[tid] = asum;
    __syncthreads();
    for (int s = 128; s > 0; s >>= 1) {
        if (tid < s) red[tid] += red[tid + s];
        __syncthreads();
    }
    const float ainv = 1.f / red[0];
    __syncthreads();

    for (int m = tid; m < N_; m += 256) row[m] = buf[m] * ainv;
}

// ================ AV wmma GEMM: g_o = attn @ V ===============================
// per block: 128 rows x 48 cols; 4 warps, each 32 rows x 48 cols (2x3 tiles).
__global__ void __launch_bounds__(128) av_tc(const float* __restrict__ attn) {
    __shared__ __nv_bfloat16 sAh[128 * 16], sAl[128 * 16];

    const int tid = threadIdx.x;
    const int w = tid >> 5;
    const int bh = blockIdx.y;
    const int b = bh >> 4;
    const int h = bh & 15;
    const int r0 = blockIdx.x * 128;

    const float* abase = attn + (size_t)bh * N_ * N_;
    const __nv_bfloat16* vhb = g_vh + (size_t)bh * N_ * D_;
    const __nv_bfloat16* vlb = g_vl + (size_t)bh * N_ * D_;

    wmma::fragment<wmma::accumulator, 16, 16, 16, float> acc[2][3];
#pragma unroll
    for (int i = 0; i < 2; i++)
#pragma unroll
        for (int j = 0; j < 3; j++) wmma::fill_fragment(acc[i][j], 0.f);

    for (int k0 = 0; k0 < N_; k0 += 16) {
        __syncthreads();
        // load + split attn tile [128][16]
#pragma unroll
        for (int it = 0; it < 4; it++) {
            const int v = tid + it * 128;
            const int row = v >> 2;
            const int c4 = (v & 3) * 4;
            const int gr = min(r0 + row, N_ - 1);
            float4 a4 = *(const float4*)(abase + (size_t)gr * N_ + k0 + c4);
            float vs[4] = {a4.x, a4.y, a4.z, a4.w};
            __nv_bfloat16 hh[4], ll[4];
#pragma unroll
            for (int q = 0; q < 4; q++) {
                hh[q] = __float2bfloat16(vs[q]);
                ll[q] = __float2bfloat16(vs[q] - __bfloat162float(hh[q]));
            }
            *(uint2*)&sAh[row * 16 + c4] = *(uint2*)hh;
            *(uint2*)&sAl[row * 16 + c4] = *(uint2*)ll;
        }
        __syncthreads();

        wmma::fragment<wmma::matrix_a, 16, 16, 16, __nv_bfloat16, wmma::row_major> fah[2], fal[2];
        wmma::fragment<wmma::matrix_b, 16, 16, 16, __nv_bfloat16, wmma::row_major> fbh[3], fbl[3];
#pragma unroll
        for (int i = 0; i < 2; i++) {
            const int r = w * 32 + i * 16;
            wmma::load_matrix_sync(fah[i], &sAh[r * 16], 16);
            wmma::load_matrix_sync(fal[i], &sAl[r * 16], 16);
        }
#pragma unroll
        for (int j = 0; j < 3; j++) {
            wmma::load_matrix_sync(fbh[j], vhb + (size_t)k0 * D_ + j * 16, D_);
            wmma::load_matrix_sync(fbl[j], vlb + (size_t)k0 * D_ + j * 16, D_);
        }
#pragma unroll
        for (int i = 0; i < 2; i++)
#pragma unroll
            for (int j = 0; j < 3; j++) {
                wmma::mma_sync(acc[i][j], fah[i], fbh[j], acc[i][j]);
                wmma::mma_sync(acc[i][j], fah[i], fbl[j], acc[i][j]);
                wmma::mma_sync(acc[i][j], fal[i], fbh[j], acc[i][j]);
            }
    }

#pragma unroll
    for (int i = 0; i < 2; i++) {
        const int row = r0 + w * 32 + i * 16;
        if (row >= N_) continue;
#pragma unroll
        for (int j = 0; j < 3; j++) {
            wmma::store_matrix_sync(g_o + (size_t)(b * N_ + row) * C_ + h * D_ + j * 16,
                                    acc[i][j], C_, wmma::mem_row_major);
        }
    }
}

// ---------------- launch ----------------------------------------------------
extern "C" void kernel_launch(void* const* d_in, const int* in_sizes, int n_in,
                              void* d_out, int out_size) {
    const float* x      = (const float*)d_in[0];
    const float* Wq     = (const float*)d_in[1];
    const float* Wk     = (const float*)d_in[2];
    const float* Wv     = (const float*)d_in[3];
    const float* Wproj  = (const float*)d_in[4];
    const float* b_proj = (const float*)d_in[5];
    const float* W_pos  = (const float*)d_in[6];
    const float* b_pos  = (const float*)d_in[7];
    const float* gating = (const float*)d_in[8];

    float* out_o    = (float*)d_out;                              // [B,N,C]
    float* out_attn = out_o + (size_t)B_ * N_ * C_;               // [B,H,N,N]
    float* out_v    = out_attn + (size_t)B_ * H_ * N_ * N_;       // [B,H,N,D]

    split_x<<<(M_ * C_ / 4 + 255) / 256, 256>>>(x);
    split_w<<<dim3((C_ * C_ / 4 + 255) / 256, 4), 256>>>(Wq, Wk, Wv, Wproj);

    tc_gemm<<<dim3(C_ / 128, M_ / 128, 3), 256>>>(0, nullptr, out_v);

    pos_kernel<<<dim3(N_, H_), 256>>>(W_pos, b_pos);

    qk_gemm<<<dim3(7, 7, BH_), 256>>>(out_attn);

    softmax_gate<<<dim3(N_, BH_), 256>>>(gating, out_attn);

    av_tc<<<dim3(7, BH_), 128>>>(out_attn);

    split_o<<<(M_ * C_ / 4 + 255) / 256, 256>>>();

    tc_gemm<<<dim3(C_ / 128, M_ / 128, 1), 256>>>(1, out_o, nullptr);

    bias_add<<<(M_ * C_ / 4 + 255) / 256, 256>>>(out_o, b_proj);
}

// round 7
// speedup vs baseline: 3.4222x; 1.2869x over previous
#include <cuda_runtime.h>
#include <cuda_bf16.h>
#include <mma.h>
#include <cstddef>
#include <cstdint>

using namespace nvcuda;

// Problem constants
#define B_ 8
#define N_ 784
#define C_ 768
#define H_ 16
#define D_ 48
#define S_ 28
#define M_ (B_ * N_)          // 6272 rows
#define BH_ (B_ * H_)         // 128
#define SCALE_ 0.14433756729740643f  // 48^-0.5

// ---------------- scratch (device globals; no allocation allowed) ----------
__device__ float g_pos[(size_t)H_ * N_ * N_];  // softmaxed positional scores
__device__ float g_psum[(size_t)BH_ * 7 * N_]; // per-colblock exp row sums
__device__ __nv_bfloat16 g_xh[(size_t)M_ * C_], g_xl[(size_t)M_ * C_];
__device__ __nv_bfloat16 g_wh[4 * (size_t)C_ * C_], g_wl[4 * (size_t)C_ * C_];
__device__ __nv_bfloat16 g_oh[(size_t)M_ * C_], g_ol[(size_t)M_ * C_];
// per-head split operands: [bh][n][48]
__device__ __nv_bfloat16 g_qh[(size_t)BH_ * N_ * D_], g_ql[(size_t)BH_ * N_ * D_];
__device__ __nv_bfloat16 g_kh[(size_t)BH_ * N_ * D_], g_kl[(size_t)BH_ * N_ * D_];
__device__ __nv_bfloat16 g_vh[(size_t)BH_ * N_ * D_], g_vl[(size_t)BH_ * N_ * D_];

// ---------------- fp32 -> (hi, lo) bf16 split kernels -----------------------
__device__ __forceinline__ void split4(const float* src, __nv_bfloat16* hi,
                                       __nv_bfloat16* lo, size_t i4) {
    float4 v = *(const float4*)(src + i4 * 4);
    float vs[4] = {v.x, v.y, v.z, v.w};
    __nv_bfloat16 h[4], l[4];
#pragma unroll
    for (int j = 0; j < 4; j++) {
        h[j] = __float2bfloat16(vs[j]);
        l[j] = __float2bfloat16(vs[j] - __bfloat162float(h[j]));
    }
    *(uint2*)(hi + i4 * 4) = *(uint2*)h;
    *(uint2*)(lo + i4 * 4) = *(uint2*)l;
}

__global__ void __launch_bounds__(256) split_x(const float* __restrict__ x) {
    size_t i = (size_t)blockIdx.x * 256 + threadIdx.x;
    if (i < (size_t)M_ * C_ / 4) split4(x, g_xh, g_xl, i);
}
__global__ void __launch_bounds__(256) split_w(const float* __restrict__ Wq,
                                               const float* __restrict__ Wk,
                                               const float* __restrict__ Wv,
                                               const float* __restrict__ Wp) {
    const int z = blockIdx.y;
    const float* src = (z == 0) ? Wq : (z == 1) ? Wk : (z == 2) ? Wv : Wp;
    size_t i = (size_t)blockIdx.x * 256 + threadIdx.x;
    if (i < (size_t)C_ * C_ / 4)
        split4(src, g_wh + (size_t)z * C_ * C_, g_wl + (size_t)z * C_ * C_, i);
}

// ================= wmma split-bf16 GEMM (128x128 block tile) ================
// C[i,j] = sum_k A[i,k]*B[j,k]  via  Ah*Bh + Ah*Bl + Al*Bh  (fp32 accum)
// mode 0: qkv — epilogue scatters into qh/ql | kh/kl | out_v + vh/vl
// mode 1: proj — staged store with bias into outC
#define TSTR 40   // smem tile stride (bf16 elems)

__global__ void __launch_bounds__(256) tc_gemm(int mode, float* __restrict__ outC,
                                               float* __restrict__ out_v,
                                               const float* __restrict__ bias) {
    __shared__ __nv_bfloat16 sAh[128 * TSTR], sAl[128 * TSTR];
    __shared__ __nv_bfloat16 sBh[128 * TSTR], sBl[128 * TSTR];
    __shared__ float stage[8][256];

    const int tid = threadIdx.x;
    const int w = tid >> 5;
    const int lid = tid & 31;
    const int wm = w & 1;          // 0..1  (64 rows each)
    const int wn = w >> 1;         // 0..3  (32 cols each)
    const int j0 = blockIdx.x * 128;
    const int i0 = blockIdx.y * 128;
    const int z = blockIdx.z;

    const __nv_bfloat16 *Ah, *Al, *Bh, *Bl;
    if (mode == 0) {
        Ah = g_xh; Al = g_xl;
        Bh = g_wh + (size_t)z * C_ * C_; Bl = g_wl + (size_t)z * C_ * C_;
    } else {
        Ah = g_oh; Al = g_ol;
        Bh = g_wh + (size_t)3 * C_ * C_; Bl = g_wl + (size_t)3 * C_ * C_;
    }

    wmma::fragment<wmma::accumulator, 16, 16, 16, float> acc[4][2];
#pragma unroll
    for (int i = 0; i < 4; i++)
#pragma unroll
        for (int j = 0; j < 2; j++) wmma::fill_fragment(acc[i][j], 0.f);

    const int prow = tid >> 2;            // 0..63
    const int pseg = (tid & 3) * 8;       // bf16 offset within 32

    uint4 ra[2], rb[2], rc[2], rd[2];
    // prologue: load chunk 0 into regs
#pragma unroll
    for (int it = 0; it < 2; it++) {
        const int row = prow + it * 64;
        ra[it] = *(const uint4*)(Ah + (size_t)(i0 + row) * C_ + pseg);
        rb[it] = *(const uint4*)(Al + (size_t)(i0 + row) * C_ + pseg);
        rc[it] = *(const uint4*)(Bh + (size_t)(j0 + row) * C_ + pseg);
        rd[it] = *(const uint4*)(Bl + (size_t)(j0 + row) * C_ + pseg);
    }

    for (int k0 = 0; k0 < C_; k0 += 32) {
#pragma unroll
        for (int it = 0; it < 2; it++) {
            const int row = prow + it * 64;
            const int dst = row * TSTR + pseg;
            *(uint4*)&sAh[dst] = ra[it];
            *(uint4*)&sAl[dst] = rb[it];
            *(uint4*)&sBh[dst] = rc[it];
            *(uint4*)&sBl[dst] = rd[it];
        }
        __syncthreads();
        if (k0 + 32 < C_) {
#pragma unroll
            for (int it = 0; it < 2; it++) {
                const int row = prow + it * 64;
                ra[it] = *(const uint4*)(Ah + (size_t)(i0 + row) * C_ + k0 + 32 + pseg);
                rb[it] = *(const uint4*)(Al + (size_t)(i0 + row) * C_ + k0 + 32 + pseg);
                rc[it] = *(const uint4*)(Bh + (size_t)(j0 + row) * C_ + k0 + 32 + pseg);
                rd[it] = *(const uint4*)(Bl + (size_t)(j0 + row) * C_ + k0 + 32 + pseg);
            }
        }

#pragma unroll
        for (int ks = 0; ks < 2; ks++) {
            const int kk = ks * 16;
            wmma::fragment<wmma::matrix_a, 16, 16, 16, __nv_bfloat16, wmma::row_major> fah[4], fal[4];
            wmma::fragment<wmma::matrix_b, 16, 16, 16, __nv_bfloat16, wmma::col_major> fbh[2], fbl[2];
#pragma unroll
            for (int i = 0; i < 4; i++) {
                const int r = wm * 64 + i * 16;
                wmma::load_matrix_sync(fah[i], &sAh[r * TSTR + kk], TSTR);
                wmma::load_matrix_sync(fal[i], &sAl[r * TSTR + kk], TSTR);
            }
#pragma unroll
            for (int j = 0; j < 2; j++) {
                const int c = wn * 32 + j * 16;
                wmma::load_matrix_sync(fbh[j], &sBh[c * TSTR + kk], TSTR);
                wmma::load_matrix_sync(fbl[j], &sBl[c * TSTR + kk], TSTR);
            }
#pragma unroll
            for (int i = 0; i < 4; i++)
#pragma unroll
                for (int j = 0; j < 2; j++) {
                    wmma::mma_sync(acc[i][j], fah[i], fbh[j], acc[i][j]);
                    wmma::mma_sync(acc[i][j], fah[i], fbl[j], acc[i][j]);
                    wmma::mma_sync(acc[i][j], fal[i], fbh[j], acc[i][j]);
                }
        }
        __syncthreads();
    }

    if (mode == 1) {
        // staged store + bias
#pragma unroll
        for (int i = 0; i < 4; i++) {
            const int row0 = i0 + wm * 64 + i * 16;
#pragma unroll
            for (int j = 0; j < 2; j++) {
                const int col0 = j0 + wn * 32 + j * 16;
                __syncwarp();
                wmma::store_matrix_sync(&stage[w][0], acc[i][j], 16, wmma::mem_row_major);
                __syncwarp();
#pragma unroll
                for (int tt = 0; tt < 8; tt++) {
                    const int idx = tt * 32 + lid;
                    const int r = idx >> 4;
                    const int c = idx & 15;
                    outC[(size_t)(row0 + r) * C_ + col0 + c] = stage[w][idx] + bias[col0 + c];
                }
            }
        }
        return;
    }

    // mode 0 epilogue: stage each fragment, scatter to per-head split buffers
#pragma unroll
    for (int i = 0; i < 4; i++) {
        const int row0 = i0 + wm * 64 + i * 16;
#pragma unroll
        for (int j = 0; j < 2; j++) {
            const int col0 = j0 + wn * 32 + j * 16;
            __syncwarp();
            wmma::store_matrix_sync(&stage[w][0], acc[i][j], 16, wmma::mem_row_major);
            __syncwarp();
#pragma unroll
            for (int tt = 0; tt < 8; tt++) {
                const int idx = tt * 32 + lid;
                float v = stage[w][idx];
                const int grow = row0 + (idx >> 4);
                const int gcol = col0 + (idx & 15);
                const int b = grow / N_;
                const int n = grow % N_;
                const int h = gcol / D_;
                const int d = gcol % D_;
                const size_t dst = ((size_t)(b * H_ + h) * N_ + n) * D_ + d;
                if (z == 0) {
                    v *= SCALE_;
                    __nv_bfloat16 hi = __float2bfloat16(v);
                    g_qh[dst] = hi;
                    g_ql[dst] = __float2bfloat16(v - __bfloat162float(hi));
                } else if (z == 1) {
                    __nv_bfloat16 hi = __float2bfloat16(v);
                    g_kh[dst] = hi;
                    g_kl[dst] = __float2bfloat16(v - __bfloat162float(hi));
                } else {
                    out_v[dst] = v;
                    __nv_bfloat16 hi = __float2bfloat16(v);
                    g_vh[dst] = hi;
                    g_vl[dst] = __float2bfloat16(v - __bfloat162float(hi));
                }
            }
        }
    }
}

// ================ QK^T wmma GEMM -> E = exp(score) + partial row sums =======
// per bh: s[n,m] = q[n,:].k[m,:] (scale pre-folded into q). 128x128 tiles.
#define QSTR 48

__global__ void __launch_bounds__(256) qk_gemm(float* __restrict__ attn) {
    __shared__ char qsm[49152];
    __nv_bfloat16* sQh = (__nv_bfloat16*)qsm;
    __nv_bfloat16* sQl = (__nv_bfloat16*)(qsm + 12288);
    __nv_bfloat16* sKh = (__nv_bfloat16*)(qsm + 24576);
    __nv_bfloat16* sKl = (__nv_bfloat16*)(qsm + 36864);
    float (*stage)[256] = (float(*)[256])qsm;          // overlay (post-mma)
    float* partial = (float*)(qsm + 32768);            // [4][128] overlay

    const int tid = threadIdx.x;
    const int w = tid >> 5;
    const int lid = tid & 31;
    const int wm = w & 1;
    const int wn = w >> 1;
    const int m0 = blockIdx.x * 128;
    const int n0 = blockIdx.y * 128;
    const int bh = blockIdx.z;

    const __nv_bfloat16* qb = g_qh + (size_t)bh * N_ * D_;
    const __nv_bfloat16* qlb = g_ql + (size_t)bh * N_ * D_;
    const __nv_bfloat16* kb = g_kh + (size_t)bh * N_ * D_;
    const __nv_bfloat16* klb = g_kl + (size_t)bh * N_ * D_;

#pragma unroll
    for (int it = 0; it < 3; it++) {
        const int v = tid + it * 256;
        const int row = v / 6;
        const int seg = (v % 6) * 8;
        const int qrow = min(n0 + row, N_ - 1);
        const int krow = min(m0 + row, N_ - 1);
        const int dst = row * QSTR + seg;
        *(uint4*)&sQh[dst] = *(const uint4*)(qb + (size_t)qrow * D_ + seg);
        *(uint4*)&sQl[dst] = *(const uint4*)(qlb + (size_t)qrow * D_ + seg);
        *(uint4*)&sKh[dst] = *(const uint4*)(kb + (size_t)krow * D_ + seg);
        *(uint4*)&sKl[dst] = *(const uint4*)(klb + (size_t)krow * D_ + seg);
    }
    __syncthreads();

    wmma::fragment<wmma::accumulator, 16, 16, 16, float> acc[4][2];
#pragma unroll
    for (int i = 0; i < 4; i++)
#pragma unroll
        for (int j = 0; j < 2; j++) wmma::fill_fragment(acc[i][j], 0.f);

#pragma unroll
    for (int ks = 0; ks < 3; ks++) {
        const int kk = ks * 16;
        wmma::fragment<wmma::matrix_a, 16, 16, 16, __nv_bfloat16, wmma::row_major> fah[4], fal[4];
        wmma::fragment<wmma::matrix_b, 16, 16, 16, __nv_bfloat16, wmma::col_major> fbh[2], fbl[2];
#pragma unroll
        for (int i = 0; i < 4; i++) {
            const int r = wm * 64 + i * 16;
            wmma::load_matrix_sync(fah[i], &sQh[r * QSTR + kk], QSTR);
            wmma::load_matrix_sync(fal[i], &sQl[r * QSTR + kk], QSTR);
        }
#pragma unroll
        for (int j = 0; j < 2; j++) {
            const int c = wn * 32 + j * 16;
            wmma::load_matrix_sync(fbh[j], &sKh[c * QSTR + kk], QSTR);
            wmma::load_matrix_sync(fbl[j], &sKl[c * QSTR + kk], QSTR);
        }
#pragma unroll
        for (int i = 0; i < 4; i++)
#pragma unroll
            for (int j = 0; j < 2; j++) {
                wmma::mma_sync(acc[i][j], fah[i], fbh[j], acc[i][j]);
                wmma::mma_sync(acc[i][j], fah[i], fbl[j], acc[i][j]);
                wmma::mma_sync(acc[i][j], fal[i], fbh[j], acc[i][j]);
            }
    }

    __syncthreads();   // smem tiles -> stage/partial overlay

    float* abase = attn + (size_t)bh * N_ * N_;
#pragma unroll
    for (int i = 0; i < 4; i++) {
        const int row0 = n0 + wm * 64 + i * 16;
        const bool rowok = (row0 < N_);
        float rs[8];
#pragma unroll
        for (int tt = 0; tt < 8; tt++) rs[tt] = 0.f;
#pragma unroll
        for (int j = 0; j < 2; j++) {
            const int col0 = m0 + wn * 32 + j * 16;
            const bool colok = (col0 < N_);
            __syncwarp();
            wmma::store_matrix_sync(&stage[w][0], acc[i][j], 16, wmma::mem_row_major);
            __syncwarp();
            if (colok) {
#pragma unroll
                for (int tt = 0; tt < 8; tt++) {
                    const int idx = tt * 32 + lid;
                    const float e = __expf(stage[w][idx]);
                    rs[tt] += e;
                    if (rowok) {
                        const int r = row0 + (idx >> 4);
                        const int c = col0 + (idx & 15);
                        abase[(size_t)r * N_ + c] = e;
                    }
                }
            }
        }
        // reduce 16-lane groups, leaders write partial
#pragma unroll
        for (int tt = 0; tt < 8; tt++) {
            float v = rs[tt];
            v += __shfl_xor_sync(0xffffffffu, v, 1);
            v += __shfl_xor_sync(0xffffffffu, v, 2);
            v += __shfl_xor_sync(0xffffffffu, v, 4);
            v += __shfl_xor_sync(0xffffffffu, v, 8);
            if ((lid & 15) == 0) {
                const int rl = wm * 64 + i * 16 + tt * 2 + (lid >> 4);
                partial[wn * 128 + rl] = v;
            }
        }
    }
    __syncthreads();
    if (tid < 128) {
        const int n = n0 + tid;
        if (n < N_) {
            g_psum[((size_t)bh * 7 + blockIdx.x) * N_ + n] =
                partial[tid] + partial[128 + tid] + partial[256 + tid] + partial[384 + tid];
        }
    }
}

// ---------------- positional scores: softmax over m of (rel . W_pos + b) ---
__global__ void __launch_bounds__(256) pos_kernel(const float* __restrict__ W_pos,
                                                  const float* __restrict__ b_pos) {
    const int n = blockIdx.x;
    const int h = blockIdx.y;
    const int i1 = n / S_;
    const int j1 = n % S_;
    const float w0 = W_pos[h * 3 + 0];
    const float w1 = W_pos[h * 3 + 1];
    const float w2 = W_pos[h * 3 + 2];
    const float bp = b_pos[h];

    __shared__ float buf[N_];
    __shared__ float red[256];
    const int tid = threadIdx.x;

    float lmax = -1e30f;
    for (int m = tid; m < N_; m += 256) {
        float dx = (float)(m % S_ - j1);
        float dy = (float)(m / S_ - i1);
        float l = w0 * dx + w1 * dy + w2 * (dx * dx + dy * dy) + bp;
        buf[m] = l;
        lmax = fmaxf(lmax, l);
    }
    red[tid] = lmax;
    __syncthreads();
    for (int s = 128; s > 0; s >>= 1) {
        if (tid < s) red[tid] = fmaxf(red[tid], red[tid + s]);
        __syncthreads();
    }
    const float mx = red[0];
    __syncthreads();

    float lsum = 0.f;
    for (int m = tid; m < N_; m += 256) {
        float e = __expf(buf[m] - mx);
        buf[m] = e;
        lsum += e;
    }
    red[tid] = lsum;
    __syncthreads();
    for (int s = 128; s > 0; s >>= 1) {
        if (tid < s) red[tid] += red[tid + s];
        __syncthreads();
    }
    const float inv = 1.f / red[0];
    __syncthreads();

    float* row = g_pos + ((size_t)h * N_ + n) * N_;
    for (int m = tid; m < N_; m += 256) row[m] = buf[m] * inv;
}

// ======== fused: finalize attn ((1-g)E/S + g*pos, renorm==1) + AV + o-split =
// block: 112-row stripe of one bh. 256 threads = 8 warps (7 do wmma AV).
__global__ void __launch_bounds__(256) fused_av(const float* __restrict__ gating,
                                                float* __restrict__ attn) {
    __shared__ float scoef[112];
    __shared__ __nv_bfloat16 sAh[112 * 16], sAl[112 * 16];
    __shared__ float ostage[7][256];

    const int tid = threadIdx.x;
    const int w = tid >> 5;
    const int lid = tid & 31;
    const int bh = blockIdx.y;
    const int b = bh >> 4;
    const int h = bh & 15;
    const int r0 = blockIdx.x * 112;

    const float g = 1.f / (1.f + __expf(-gating[h]));

    for (int row = tid; row < 112; row += 256) {
        float S = 0.f;
#pragma unroll
        for (int mb = 0; mb < 7; mb++)
            S += g_psum[((size_t)bh * 7 + mb) * N_ + r0 + row];
        scoef[row] = (1.f - g) / S;
    }
    __syncthreads();

    float* abase = attn + (size_t)bh * N_ * N_;
    const float* pbase = g_pos + (size_t)h * N_ * N_;
    const __nv_bfloat16* vhb = g_vh + (size_t)bh * N_ * D_;
    const __nv_bfloat16* vlb = g_vl + (size_t)bh * N_ * D_;

    wmma::fragment<wmma::accumulator, 16, 16, 16, float> acc[3];
#pragma unroll
    for (int j = 0; j < 3; j++) wmma::fill_fragment(acc[j], 0.f);

    for (int k0 = 0; k0 < N_; k0 += 16) {
#pragma unroll
        for (int it = 0; it < 2; it++) {
            const int v = tid + it * 256;
            if (v < 448) {
                const int row = v >> 2;
                const int c4 = (v & 3) << 2;
                const size_t gidx = (size_t)(r0 + row) * N_ + k0 + c4;
                float4 E = *(const float4*)(abase + gidx);
                float4 p = *(const float4*)(pbase + gidx);
                const float cf = scoef[row];
                float4 a;
                a.x = cf * E.x + g * p.x;
                a.y = cf * E.y + g * p.y;
                a.z = cf * E.z + g * p.z;
                a.w = cf * E.w + g * p.w;
                *(float4*)(abase + gidx) = a;
                float vs[4] = {a.x, a.y, a.z, a.w};
                __nv_bfloat16 hh[4], ll[4];
#pragma unroll
                for (int q = 0; q < 4; q++) {
                    hh[q] = __float2bfloat16(vs[q]);
                    ll[q] = __float2bfloat16(vs[q] - __bfloat162float(hh[q]));
                }
                *(uint2*)&sAh[row * 16 + c4] = *(uint2*)hh;
                *(uint2*)&sAl[row * 16 + c4] = *(uint2*)ll;
            }
        }
        __syncthreads();

        if (w < 7) {
            wmma::fragment<wmma::matrix_a, 16, 16, 16, __nv_bfloat16, wmma::row_major> fah, fal;
            wmma::fragment<wmma::matrix_b, 16, 16, 16, __nv_bfloat16, wmma::row_major> fbh, fbl;
            wmma::load_matrix_sync(fah, &sAh[(w * 16) * 16], 16);
            wmma::load_matrix_sync(fal, &sAl[(w * 16) * 16], 16);
#pragma unroll
            for (int j = 0; j < 3; j++) {
                wmma::load_matrix_sync(fbh, vhb + (size_t)k0 * D_ + j * 16, D_);
                wmma::load_matrix_sync(fbl, vlb + (size_t)k0 * D_ + j * 16, D_);
                wmma::mma_sync(acc[j], fah, fbh, acc[j]);
                wmma::mma_sync(acc[j], fah, fbl, acc[j]);
                wmma::mma_sync(acc[j], fal, fbh, acc[j]);
            }
        }
        __syncthreads();
    }

    // epilogue: write o directly as bf16 hi/lo splits (input to proj GEMM)
    if (w < 7) {
#pragma unroll
        for (int j = 0; j < 3; j++) {
            __syncwarp();
            wmma::store_matrix_sync(&ostage[w][0], acc[j], 16, wmma::mem_row_major);
            __syncwarp();
#pragma unroll
            for (int tt = 0; tt < 8; tt++) {
                const int idx = tt * 32 + lid;
                const float v = ostage[w][idx];
                const int row = r0 + w * 16 + (idx >> 4);
                const int col = h * D_ + j * 16 + (idx & 15);
                const size_t dst = (size_t)(b * N_ + row) * C_ + col;
                __nv_bfloat16 hi = __float2bfloat16(v);
                g_oh[dst] = hi;
                g_ol[dst] = __float2bfloat16(v - __bfloat162float(hi));
            }
        }
    }
}

// ---------------- launch ----------------------------------------------------
extern "C" void kernel_launch(void* const* d_in, const int* in_sizes, int n_in,
                              void* d_out, int out_size) {
    const float* x      = (const float*)d_in[0];
    const float* Wq     = (const float*)d_in[1];
    const float* Wk     = (const float*)d_in[2];
    const float* Wv     = (const float*)d_in[3];
    const float* Wproj  = (const float*)d_in[4];
    const float* b_proj = (const float*)d_in[5];
    const float* W_pos  = (const float*)d_in[6];
    const float* b_pos  = (const float*)d_in[7];
    const float* gating = (const float*)d_in[8];

    float* out_o    = (float*)d_out;                              // [B,N,C]
    float* out_attn = out_o + (size_t)B_ * N_ * C_;               // [B,H,N,N]
    float* out_v    = out_attn + (size_t)B_ * H_ * N_ * N_;       // [B,H,N,D]

    split_x<<<(M_ * C_ / 4 + 255) / 256, 256>>>(x);
    split_w<<<dim3((C_ * C_ / 4 + 255) / 256, 4), 256>>>(Wq, Wk, Wv, Wproj);

    tc_gemm<<<dim3(C_ / 128, M_ / 128, 3), 256>>>(0, nullptr, out_v, nullptr);

    pos_kernel<<<dim3(N_, H_), 256>>>(W_pos, b_pos);

    qk_gemm<<<dim3(7, 7, BH_), 256>>>(out_attn);

    fused_av<<<dim3(7, BH_), 256>>>(gating, out_attn);

    tc_gemm<<<dim3(C_ / 128, M_ / 128, 1), 256>>>(1, out_o, nullptr, b_proj);
}

// round 8
// speedup vs baseline: 3.5467x; 1.0364x over previous
#include <cuda_runtime.h>
#include <cuda_bf16.h>
#include <mma.h>
#include <cstddef>
#include <cstdint>

using namespace nvcuda;

// Problem constants
#define B_ 8
#define N_ 784
#define C_ 768
#define H_ 16
#define D_ 48
#define S_ 28
#define M_ (B_ * N_)          // 6272 rows
#define BH_ (B_ * H_)         // 128
#define SCALE_ 0.14433756729740643f  // 48^-0.5

__device__ __forceinline__ uint32_t smem_u32(const void* p) {
    uint32_t a;
    asm("{ .reg .u64 t; cvta.to.shared.u64 t, %1; cvt.u32.u64 %0, t; }" : "=r"(a) : "l"(p));
    return a;
}
#define CP16(dst, src) \
    asm volatile("cp.async.ca.shared.global [%0], [%1], 16;" :: "r"(dst), "l"(src))
#define CP_COMMIT() asm volatile("cp.async.commit_group;")
#define CP_WAIT1()  asm volatile("cp.async.wait_group 1;")
#define CP_WAIT0()  asm volatile("cp.async.wait_group 0;")

__device__ __forceinline__ uint32_t pack_bf16x2(float lo, float hi) {
    uint32_t r;
    asm("cvt.rn.bf16x2.f32 %0, %1, %2;" : "=r"(r) : "f"(hi), "f"(lo));
    return r;
}
__device__ __forceinline__ float bfx2_lo(uint32_t pk) { return __uint_as_float(pk << 16); }
__device__ __forceinline__ float bfx2_hi(uint32_t pk) { return __uint_as_float(pk & 0xFFFF0000u); }

// ---------------- scratch (device globals; no allocation allowed) ----------
__device__ float g_pos[(size_t)H_ * N_ * N_];  // softmaxed positional scores
__device__ float g_psum[(size_t)BH_ * 7 * N_]; // per-colblock exp row sums
__device__ __nv_bfloat16 g_xh[(size_t)M_ * C_], g_xl[(size_t)M_ * C_];
__device__ __nv_bfloat16 g_wh[4 * (size_t)C_ * C_], g_wl[4 * (size_t)C_ * C_];
__device__ __nv_bfloat16 g_oh[(size_t)M_ * C_], g_ol[(size_t)M_ * C_];
// per-head split operands: [bh][n][48]
__device__ __nv_bfloat16 g_qh[(size_t)BH_ * N_ * D_], g_ql[(size_t)BH_ * N_ * D_];
__device__ __nv_bfloat16 g_kh[(size_t)BH_ * N_ * D_], g_kl[(size_t)BH_ * N_ * D_];
__device__ __nv_bfloat16 g_vh[(size_t)BH_ * N_ * D_], g_vl[(size_t)BH_ * N_ * D_];

// ---------------- fp32 -> (hi, lo) bf16 split kernels -----------------------
__device__ __forceinline__ void split4(const float* src, __nv_bfloat16* hi,
                                       __nv_bfloat16* lo, size_t i4) {
    float4 v = *(const float4*)(src + i4 * 4);
    uint32_t h01 = pack_bf16x2(v.x, v.y);
    uint32_t h23 = pack_bf16x2(v.z, v.w);
    uint32_t l01 = pack_bf16x2(v.x - bfx2_lo(h01), v.y - bfx2_hi(h01));
    uint32_t l23 = pack_bf16x2(v.z - bfx2_lo(h23), v.w - bfx2_hi(h23));
    *(uint2*)(hi + i4 * 4) = make_uint2(h01, h23);
    *(uint2*)(lo + i4 * 4) = make_uint2(l01, l23);
}

__global__ void __launch_bounds__(256) split_x(const float* __restrict__ x) {
    size_t i = (size_t)blockIdx.x * 256 + threadIdx.x;
    if (i < (size_t)M_ * C_ / 4) split4(x, g_xh, g_xl, i);
}
__global__ void __launch_bounds__(256) split_w(const float* __restrict__ Wq,
                                               const float* __restrict__ Wk,
                                               const float* __restrict__ Wv,
                                               const float* __restrict__ Wp) {
    const int z = blockIdx.y;
    const float* src = (z == 0) ? Wq : (z == 1) ? Wk : (z == 2) ? Wv : Wp;
    size_t i = (size_t)blockIdx.x * 256 + threadIdx.x;
    if (i < (size_t)C_ * C_ / 4)
        split4(src, g_wh + (size_t)z * C_ * C_, g_wl + (size_t)z * C_ * C_, i);
}

// ================= wmma split-bf16 GEMM, cp.async double buffered ===========
// C[i,j] = sum_k A[i,k]*B[j,k]  via  Ah*Bh + Ah*Bl + Al*Bh  (fp32 accum)
#define TSTR 40                   // smem tile stride (bf16 elems)
#define TCB 40960                 // bytes per stage (4 arrays x 10240)
#define TC_SMEM (2 * TCB + 8192)  // + stage floats

__global__ void __launch_bounds__(256) tc_gemm(int mode, float* __restrict__ outC,
                                               float* __restrict__ out_v,
                                               const float* __restrict__ bias) {
    extern __shared__ char gsm[];
    float (*stage)[256] = (float(*)[256])(gsm + 2 * TCB);
    const uint32_t sb = smem_u32(gsm);

    const int tid = threadIdx.x;
    const int w = tid >> 5;
    const int lid = tid & 31;
    const int wm = w & 1;          // 0..1  (64 rows each)
    const int wn = w >> 1;         // 0..3  (32 cols each)
    const int j0 = blockIdx.x * 128;
    const int i0 = blockIdx.y * 128;
    const int z = blockIdx.z;

    const __nv_bfloat16 *Ah, *Al, *Bh, *Bl;
    if (mode == 0) {
        Ah = g_xh; Al = g_xl;
        Bh = g_wh + (size_t)z * C_ * C_; Bl = g_wl + (size_t)z * C_ * C_;
    } else {
        Ah = g_oh; Al = g_ol;
        Bh = g_wh + (size_t)3 * C_ * C_; Bl = g_wl + (size_t)3 * C_ * C_;
    }

    const int prow = tid >> 2;            // 0..63
    const int pseg = (tid & 3) * 8;       // bf16 offset within 32

    wmma::fragment<wmma::accumulator, 16, 16, 16, float> acc[4][2];
#pragma unroll
    for (int i = 0; i < 4; i++)
#pragma unroll
        for (int j = 0; j < 2; j++) wmma::fill_fragment(acc[i][j], 0.f);

    // async copy issue for chunk ch into stage s
    auto issue = [&](int ch, int s) {
        const int koff = ch * 32 + pseg;
#pragma unroll
        for (int it = 0; it < 2; it++) {
            const int row = prow + it * 64;
            const uint32_t d = sb + s * TCB + (row * TSTR + pseg) * 2;
            CP16(d +     0, Ah + (size_t)(i0 + row) * C_ + koff);
            CP16(d + 10240, Al + (size_t)(i0 + row) * C_ + koff);
            CP16(d + 20480, Bh + (size_t)(j0 + row) * C_ + koff);
            CP16(d + 30720, Bl + (size_t)(j0 + row) * C_ + koff);
        }
        CP_COMMIT();
    };

    issue(0, 0);
    for (int ch = 0; ch < C_ / 32; ch++) {
        const int s = ch & 1;
        if (ch + 1 < C_ / 32) { issue(ch + 1, (ch + 1) & 1); CP_WAIT1(); }
        else                  { CP_WAIT0(); }
        __syncthreads();

        const __nv_bfloat16* bAh = (const __nv_bfloat16*)(gsm + s * TCB);
        const __nv_bfloat16* bAl = (const __nv_bfloat16*)(gsm + s * TCB + 10240);
        const __nv_bfloat16* bBh = (const __nv_bfloat16*)(gsm + s * TCB + 20480);
        const __nv_bfloat16* bBl = (const __nv_bfloat16*)(gsm + s * TCB + 30720);

#pragma unroll
        for (int ks = 0; ks < 2; ks++) {
            const int kk = ks * 16;
            wmma::fragment<wmma::matrix_a, 16, 16, 16, __nv_bfloat16, wmma::row_major> fah[4], fal[4];
            wmma::fragment<wmma::matrix_b, 16, 16, 16, __nv_bfloat16, wmma::col_major> fbh[2], fbl[2];
#pragma unroll
            for (int i = 0; i < 4; i++) {
                const int r = wm * 64 + i * 16;
                wmma::load_matrix_sync(fah[i], &bAh[r * TSTR + kk], TSTR);
                wmma::load_matrix_sync(fal[i], &bAl[r * TSTR + kk], TSTR);
            }
#pragma unroll
            for (int j = 0; j < 2; j++) {
                const int c = wn * 32 + j * 16;
                wmma::load_matrix_sync(fbh[j], &bBh[c * TSTR + kk], TSTR);
                wmma::load_matrix_sync(fbl[j], &bBl[c * TSTR + kk], TSTR);
            }
#pragma unroll
            for (int i = 0; i < 4; i++)
#pragma unroll
                for (int j = 0; j < 2; j++) {
                    wmma::mma_sync(acc[i][j], fah[i], fbh[j], acc[i][j]);
                    wmma::mma_sync(acc[i][j], fah[i], fbl[j], acc[i][j]);
                    wmma::mma_sync(acc[i][j], fal[i], fbh[j], acc[i][j]);
                }
        }
        __syncthreads();
    }

    if (mode == 1) {
#pragma unroll
        for (int i = 0; i < 4; i++) {
            const int row0 = i0 + wm * 64 + i * 16;
#pragma unroll
            for (int j = 0; j < 2; j++) {
                const int col0 = j0 + wn * 32 + j * 16;
                __syncwarp();
                wmma::store_matrix_sync(&stage[w][0], acc[i][j], 16, wmma::mem_row_major);
                __syncwarp();
#pragma unroll
                for (int tt = 0; tt < 8; tt++) {
                    const int idx = tt * 32 + lid;
                    const int r = idx >> 4;
                    const int c = idx & 15;
                    outC[(size_t)(row0 + r) * C_ + col0 + c] = stage[w][idx] + bias[col0 + c];
                }
            }
        }
        return;
    }

    // mode 0 epilogue: stage each fragment, scatter to per-head split buffers
#pragma unroll
    for (int i = 0; i < 4; i++) {
        const int row0 = i0 + wm * 64 + i * 16;
#pragma unroll
        for (int j = 0; j < 2; j++) {
            const int col0 = j0 + wn * 32 + j * 16;
            __syncwarp();
            wmma::store_matrix_sync(&stage[w][0], acc[i][j], 16, wmma::mem_row_major);
            __syncwarp();
#pragma unroll
            for (int tt = 0; tt < 8; tt++) {
                const int idx = tt * 32 + lid;
                float v = stage[w][idx];
                const int grow = row0 + (idx >> 4);
                const int gcol = col0 + (idx & 15);
                const int b = grow / N_;
                const int n = grow % N_;
                const int h = gcol / D_;
                const int d = gcol % D_;
                const size_t dst = ((size_t)(b * H_ + h) * N_ + n) * D_ + d;
                if (z == 0) {
                    v *= SCALE_;
                    __nv_bfloat16 hi = __float2bfloat16(v);
                    g_qh[dst] = hi;
                    g_ql[dst] = __float2bfloat16(v - __bfloat162float(hi));
                } else if (z == 1) {
                    __nv_bfloat16 hi = __float2bfloat16(v);
                    g_kh[dst] = hi;
                    g_kl[dst] = __float2bfloat16(v - __bfloat162float(hi));
                } else {
                    out_v[dst] = v;
                    __nv_bfloat16 hi = __float2bfloat16(v);
                    g_vh[dst] = hi;
                    g_vl[dst] = __float2bfloat16(v - __bfloat162float(hi));
                }
            }
        }
    }
}

// ================ QK^T wmma GEMM -> E = exp(score) + partial row sums =======
#define QSTR 48

__global__ void __launch_bounds__(256) qk_gemm(float* __restrict__ attn) {
    __shared__ char qsm[49152];
    __nv_bfloat16* sQh = (__nv_bfloat16*)qsm;
    __nv_bfloat16* sQl = (__nv_bfloat16*)(qsm + 12288);
    __nv_bfloat16* sKh = (__nv_bfloat16*)(qsm + 24576);
    __nv_bfloat16* sKl = (__nv_bfloat16*)(qsm + 36864);
    float (*stage)[256] = (float(*)[256])qsm;          // overlay (post-mma)
    float* partial = (float*)(qsm + 32768);            // [4][128] overlay

    const int tid = threadIdx.x;
    const int w = tid >> 5;
    const int lid = tid & 31;
    const int wm = w & 1;
    const int wn = w >> 1;
    const int m0 = blockIdx.x * 128;
    const int n0 = blockIdx.y * 128;
    const int bh = blockIdx.z;

    const __nv_bfloat16* qb = g_qh + (size_t)bh * N_ * D_;
    const __nv_bfloat16* qlb = g_ql + (size_t)bh * N_ * D_;
    const __nv_bfloat16* kb = g_kh + (size_t)bh * N_ * D_;
    const __nv_bfloat16* klb = g_kl + (size_t)bh * N_ * D_;

#pragma unroll
    for (int it = 0; it < 3; it++) {
        const int v = tid + it * 256;
        const int row = v / 6;
        const int seg = (v % 6) * 8;
        const int qrow = min(n0 + row, N_ - 1);
        const int krow = min(m0 + row, N_ - 1);
        const int dst = row * QSTR + seg;
        *(uint4*)&sQh[dst] = *(const uint4*)(qb + (size_t)qrow * D_ + seg);
        *(uint4*)&sQl[dst] = *(const uint4*)(qlb + (size_t)qrow * D_ + seg);
        *(uint4*)&sKh[dst] = *(const uint4*)(kb + (size_t)krow * D_ + seg);
        *(uint4*)&sKl[dst] = *(const uint4*)(klb + (size_t)krow * D_ + seg);
    }
    __syncthreads();

    wmma::fragment<wmma::accumulator, 16, 16, 16, float> acc[4][2];
#pragma unroll
    for (int i = 0; i < 4; i++)
#pragma unroll
        for (int j = 0; j < 2; j++) wmma::fill_fragment(acc[i][j], 0.f);

#pragma unroll
    for (int ks = 0; ks < 3; ks++) {
        const int kk = ks * 16;
        wmma::fragment<wmma::matrix_a, 16, 16, 16, __nv_bfloat16, wmma::row_major> fah[4], fal[4];
        wmma::fragment<wmma::matrix_b, 16, 16, 16, __nv_bfloat16, wmma::col_major> fbh[2], fbl[2];
#pragma unroll
        for (int i = 0; i < 4; i++) {
            const int r = wm * 64 + i * 16;
            wmma::load_matrix_sync(fah[i], &sQh[r * QSTR + kk], QSTR);
            wmma::load_matrix_sync(fal[i], &sQl[r * QSTR + kk], QSTR);
        }
#pragma unroll
        for (int j = 0; j < 2; j++) {
            const int c = wn * 32 + j * 16;
            wmma::load_matrix_sync(fbh[j], &sKh[c * QSTR + kk], QSTR);
            wmma::load_matrix_sync(fbl[j], &sKl[c * QSTR + kk], QSTR);
        }
#pragma unroll
        for (int i = 0; i < 4; i++)
#pragma unroll
            for (int j = 0; j < 2; j++) {
                wmma::mma_sync(acc[i][j], fah[i], fbh[j], acc[i][j]);
                wmma::mma_sync(acc[i][j], fah[i], fbl[j], acc[i][j]);
                wmma::mma_sync(acc[i][j], fal[i], fbh[j], acc[i][j]);
            }
    }

    __syncthreads();   // smem tiles -> stage/partial overlay

    float* abase = attn + (size_t)bh * N_ * N_;
#pragma unroll
    for (int i = 0; i < 4; i++) {
        const int row0 = n0 + wm * 64 + i * 16;
        const bool rowok = (row0 < N_);
        float rs[8];
#pragma unroll
        for (int tt = 0; tt < 8; tt++) rs[tt] = 0.f;
#pragma unroll
        for (int j = 0; j < 2; j++) {
            const int col0 = m0 + wn * 32 + j * 16;
            const bool colok = (col0 < N_);
            __syncwarp();
            wmma::store_matrix_sync(&stage[w][0], acc[i][j], 16, wmma::mem_row_major);
            __syncwarp();
            if (colok) {
#pragma unroll
                for (int tt = 0; tt < 8; tt++) {
                    const int idx = tt * 32 + lid;
                    const float e = __expf(stage[w][idx]);
                    rs[tt] += e;
                    if (rowok) {
                        const int r = row0 + (idx >> 4);
                        const int c = col0 + (idx & 15);
                        abase[(size_t)r * N_ + c] = e;
                    }
                }
            }
        }
#pragma unroll
        for (int tt = 0; tt < 8; tt++) {
            float v = rs[tt];
            v += __shfl_xor_sync(0xffffffffu, v, 1);
            v += __shfl_xor_sync(0xffffffffu, v, 2);
            v += __shfl_xor_sync(0xffffffffu, v, 4);
            v += __shfl_xor_sync(0xffffffffu, v, 8);
            if ((lid & 15) == 0) {
                const int rl = wm * 64 + i * 16 + tt * 2 + (lid >> 4);
                partial[wn * 128 + rl] = v;
            }
        }
    }
    __syncthreads();
    if (tid < 128) {
        const int n = n0 + tid;
        if (n < N_) {
            g_psum[((size_t)bh * 7 + blockIdx.x) * N_ + n] =
                partial[tid] + partial[128 + tid] + partial[256 + tid] + partial[384 + tid];
        }
    }
}

// ---------------- positional scores: softmax over m of (rel . W_pos + b) ---
__global__ void __launch_bounds__(256) pos_kernel(const float* __restrict__ W_pos,
                                                  const float* __restrict__ b_pos) {
    const int n = blockIdx.x;
    const int h = blockIdx.y;
    const int i1 = n / S_;
    const int j1 = n % S_;
    const float w0 = W_pos[h * 3 + 0];
    const float w1 = W_pos[h * 3 + 1];
    const float w2 = W_pos[h * 3 + 2];
    const float bp = b_pos[h];

    __shared__ float buf[N_];
    __shared__ float red[256];
    const int tid = threadIdx.x;

    float lmax = -1e30f;
    for (int m = tid; m < N_; m += 256) {
        float dx = (float)(m % S_ - j1);
        float dy = (float)(m / S_ - i1);
        float l = w0 * dx + w1 * dy + w2 * (dx * dx + dy * dy) + bp;
        buf[m] = l;
        lmax = fmaxf(lmax, l);
    }
    red[tid] = lmax;
    __syncthreads();
    for (int s = 128; s > 0; s >>= 1) {
        if (tid < s) red[tid] = fmaxf(red[tid], red[tid + s]);
        __syncthreads();
    }
    const float mx = red[0];
    __syncthreads();

    float lsum = 0.f;
    for (int m = tid; m < N_; m += 256) {
        float e = __expf(buf[m] - mx);
        buf[m] = e;
        lsum += e;
    }
    red[tid] = lsum;
    __syncthreads();
    for (int s = 128; s > 0; s >>= 1) {
        if (tid < s) red[tid] += red[tid + s];
        __syncthreads();
    }
    const float inv = 1.f / red[0];
    __syncthreads();

    float* row = g_pos + ((size_t)h * N_ + n) * N_;
    for (int m = tid; m < N_; m += 256) row[m] = buf[m] * inv;
}

// ======== fused: finalize attn ((1-g)E/S + g*pos) + AV + o-split ============
// grid (stripe 7, b 8, h 16) so blocks sharing pos[h] are adjacent (L2 reuse).
// chunked: 112-col chunks; elementwise finalize into smem splits, then AV.
#define FAV_SMEM (2 * 112 * 120 * 2 + 448 + 7 * 256 * 4)   // 61376

__global__ void __launch_bounds__(256) fused_av(const float* __restrict__ gating,
                                                float* __restrict__ attn) {
    extern __shared__ char fsm[];
    __nv_bfloat16* sAh = (__nv_bfloat16*)fsm;                  // [112][120]
    __nv_bfloat16* sAl = (__nv_bfloat16*)(fsm + 26880);
    float* scoef = (float*)(fsm + 53760);                      // [112]
    float (*ostage)[256] = (float(*)[256])(fsm + 54208);       // [7][256]

    const int tid = threadIdx.x;
    const int w = tid >> 5;
    const int lid = tid & 31;
    const int b = blockIdx.y;
    const int h = blockIdx.z;
    const int bh = b * H_ + h;
    const int r0 = blockIdx.x * 112;

    const float g = 1.f / (1.f + __expf(-gating[h]));

    for (int row = tid; row < 112; row += 256) {
        float S = 0.f;
#pragma unroll
        for (int mb = 0; mb < 7; mb++)
            S += g_psum[((size_t)bh * 7 + mb) * N_ + r0 + row];
        scoef[row] = (1.f - g) / S;
    }
    __syncthreads();

    float* abase = attn + (size_t)bh * N_ * N_;
    const float* pbase = g_pos + (size_t)h * N_ * N_;
    const __nv_bfloat16* vhb = g_vh + (size_t)bh * N_ * D_;
    const __nv_bfloat16* vlb = g_vl + (size_t)bh * N_ * D_;

    wmma::fragment<wmma::accumulator, 16, 16, 16, float> acc[3];
#pragma unroll
    for (int j = 0; j < 3; j++) wmma::fill_fragment(acc[j], 0.f);

    for (int c = 0; c < 7; c++) {
        const int m0 = c * 112;
        // elementwise finalize: 112 rows x 28 float4 groups
        for (int v = tid; v < 112 * 28; v += 256) {
            const int row = v / 28;
            const int cg = v - row * 28;
            const size_t gidx = (size_t)(r0 + row) * N_ + m0 + cg * 4;
            float4 E = *(const float4*)(abase + gidx);
            float4 p = *(const float4*)(pbase + gidx);
            const float cf = scoef[row];
            float4 a;
            a.x = cf * E.x + g * p.x;
            a.y = cf * E.y + g * p.y;
            a.z = cf * E.z + g * p.z;
            a.w = cf * E.w + g * p.w;
            *(float4*)(abase + gidx) = a;
            uint32_t h01 = pack_bf16x2(a.x, a.y);
            uint32_t h23 = pack_bf16x2(a.z, a.w);
            uint32_t l01 = pack_bf16x2(a.x - bfx2_lo(h01), a.y - bfx2_hi(h01));
            uint32_t l23 = pack_bf16x2(a.z - bfx2_lo(h23), a.w - bfx2_hi(h23));
            const int so = row * 120 + cg * 4;
            *(uint2*)&sAh[so] = make_uint2(h01, h23);
            *(uint2*)&sAl[so] = make_uint2(l01, l23);
        }
        __syncthreads();

        if (w < 7) {
#pragma unroll
            for (int kt = 0; kt < 7; kt++) {
                wmma::fragment<wmma::matrix_a, 16, 16, 16, __nv_bfloat16, wmma::row_major> fah, fal;
                wmma::load_matrix_sync(fah, &sAh[(w * 16) * 120 + kt * 16], 120);
                wmma::load_matrix_sync(fal, &sAl[(w * 16) * 120 + kt * 16], 120);
#pragma unroll
                for (int j = 0; j < 3; j++) {
                    wmma::fragment<wmma::matrix_b, 16, 16, 16, __nv_bfloat16, wmma::row_major> fbh, fbl;
                    wmma::load_matrix_sync(fbh, vhb + (size_t)(m0 + kt * 16) * D_ + j * 16, D_);
                    wmma::load_matrix_sync(fbl, vlb + (size_t)(m0 + kt * 16) * D_ + j * 16, D_);
                    wmma::mma_sync(acc[j], fah, fbh, acc[j]);
                    wmma::mma_sync(acc[j], fah, fbl, acc[j]);
                    wmma::mma_sync(acc[j], fal, fbh, acc[j]);
                }
            }
        }
        __syncthreads();
    }

    // epilogue: write o directly as bf16 hi/lo splits (input to proj GEMM)
    if (w < 7) {
#pragma unroll
        for (int j = 0; j < 3; j++) {
            __syncwarp();
            wmma::store_matrix_sync(&ostage[w][0], acc[j], 16, wmma::mem_row_major);
            __syncwarp();
#pragma unroll
            for (int tt = 0; tt < 8; tt++) {
                const int idx = tt * 32 + lid;
                const float v = ostage[w][idx];
                const int row = r0 + w * 16 + (idx >> 4);
                const int col = h * D_ + j * 16 + (idx & 15);
                const size_t dst = (size_t)(b * N_ + row) * C_ + col;
                __nv_bfloat16 hi = __float2bfloat16(v);
                g_oh[dst] = hi;
                g_ol[dst] = __float2bfloat16(v - __bfloat162float(hi));
            }
        }
    }
}

// ---------------- launch ----------------------------------------------------
extern "C" void kernel_launch(void* const* d_in, const int* in_sizes, int n_in,
                              void* d_out, int out_size) {
    const float* x      = (const float*)d_in[0];
    const float* Wq     = (const float*)d_in[1];
    const float* Wk     = (const float*)d_in[2];
    const float* Wv     = (const float*)d_in[3];
    const float* Wproj  = (const float*)d_in[4];
    const float* b_proj = (const float*)d_in[5];
    const float* W_pos  = (const float*)d_in[6];
    const float* b_pos  = (const float*)d_in[7];
    const float* gating = (const float*)d_in[8];

    float* out_o    = (float*)d_out;                              // [B,N,C]
    float* out_attn = out_o + (size_t)B_ * N_ * C_;               // [B,H,N,N]
    float* out_v    = out_attn + (size_t)B_ * H_ * N_ * N_;       // [B,H,N,D]

    cudaFuncSetAttribute((const void*)tc_gemm,
                         cudaFuncAttributeMaxDynamicSharedMemorySize, TC_SMEM);
    cudaFuncSetAttribute((const void*)fused_av,
                         cudaFuncAttributeMaxDynamicSharedMemorySize, FAV_SMEM);

    split_x<<<(M_ * C_ / 4 + 255) / 256, 256>>>(x);
    split_w<<<dim3((C_ * C_ / 4 + 255) / 256, 4), 256>>>(Wq, Wk, Wv, Wproj);

    tc_gemm<<<dim3(C_ / 128, M_ / 128, 3), 256, TC_SMEM>>>(0, nullptr, out_v, nullptr);

    pos_kernel<<<dim3(N_, H_), 256>>>(W_pos, b_pos);

    qk_gemm<<<dim3(7, 7, BH_), 256>>>(out_attn);

    fused_av<<<dim3(7, B_, H_), 256, FAV_SMEM>>>(gating, out_attn);

    tc_gemm<<<dim3(C_ / 128, M_ / 128, 1), 256, TC_SMEM>>>(1, out_o, nullptr, b_proj);
}